// round 3
// baseline (speedup 1.0000x reference)
#include <cuda_runtime.h>
#include <math.h>

#define BB     4
#define SS     2048
#define DM     768
#define NH     12
#define DKH    64
#define M_TOT  (BB*SS)   // 8192

// -------- scratch (static device arrays; no runtime allocation) --------
__device__ float g_q  [M_TOT*DM];
__device__ float g_k  [M_TOT*DM];
__device__ float g_v  [M_TOT*DM];
__device__ float g_ctx[M_TOT*DM];
__device__ float g_tmp[M_TOT*DM];

// ============================================================================
// GEMM: C[M,768] = A[M,768] @ W[768,768] + bias (+ optional residual)
// 128x128 tile, BK=16, 256 threads, 8x8 per thread.
// ============================================================================
template<bool RESID>
__global__ __launch_bounds__(256) void gemm_bias_kernel(
    const float* __restrict__ A, const float* __restrict__ W,
    const float* __restrict__ bias, const float* __restrict__ resid,
    float* __restrict__ C)
{
    const int N = DM, K = DM;
    __shared__ float As[16][128];   // transposed A tile: As[k][m]
    __shared__ float Bs[16][128];   // Bs[k][n]

    const int tid = threadIdx.x;
    const int m0  = blockIdx.y * 128;
    const int n0  = blockIdx.x * 128;

    const int arow = tid >> 1;          // 0..127
    const int acol = (tid & 1) * 8;     // 0 or 8
    const int brow = tid >> 4;          // 0..15
    const int bcol = (tid & 15) * 8;    // 0..120
    const int ty   = tid >> 4;          // 0..15 : rows ty*8..ty*8+7
    const int tx   = tid & 15;          // 0..15 : cols tx*8..tx*8+7

    float acc[8][8] = {};

    for (int k0 = 0; k0 < K; k0 += 16) {
        // A tile (transposed into SMEM)
        #pragma unroll
        for (int half = 0; half < 2; half++) {
            float4 av = *(const float4*)(A + (size_t)(m0 + arow) * K + k0 + acol + half * 4);
            As[acol + half * 4 + 0][arow] = av.x;
            As[acol + half * 4 + 1][arow] = av.y;
            As[acol + half * 4 + 2][arow] = av.z;
            As[acol + half * 4 + 3][arow] = av.w;
        }
        // B tile
        #pragma unroll
        for (int half = 0; half < 2; half++) {
            float4 bv = *(const float4*)(W + (size_t)(k0 + brow) * N + n0 + bcol + half * 4);
            *(float4*)&Bs[brow][bcol + half * 4] = bv;
        }
        __syncthreads();

        #pragma unroll
        for (int kk = 0; kk < 16; kk++) {
            float a[8], b[8];
            *(float4*)&a[0] = *(const float4*)&As[kk][ty * 8];
            *(float4*)&a[4] = *(const float4*)&As[kk][ty * 8 + 4];
            *(float4*)&b[0] = *(const float4*)&Bs[kk][tx * 8];
            *(float4*)&b[4] = *(const float4*)&Bs[kk][tx * 8 + 4];
            #pragma unroll
            for (int i = 0; i < 8; i++)
                #pragma unroll
                for (int j = 0; j < 8; j++)
                    acc[i][j] += a[i] * b[j];
        }
        __syncthreads();
    }

    float bi[8];
    *(float4*)&bi[0] = *(const float4*)(bias + n0 + tx * 8);
    *(float4*)&bi[4] = *(const float4*)(bias + n0 + tx * 8 + 4);
    #pragma unroll
    for (int i = 0; i < 8; i++) {
        int mrow = m0 + ty * 8 + i;
        float o[8];
        #pragma unroll
        for (int j = 0; j < 8; j++) o[j] = acc[i][j] + bi[j];
        if (RESID) {
            float4 r0 = *(const float4*)(resid + (size_t)mrow * N + n0 + tx * 8);
            float4 r1 = *(const float4*)(resid + (size_t)mrow * N + n0 + tx * 8 + 4);
            o[0] += r0.x; o[1] += r0.y; o[2] += r0.z; o[3] += r0.w;
            o[4] += r1.x; o[5] += r1.y; o[6] += r1.z; o[7] += r1.w;
        }
        *(float4*)(C + (size_t)mrow * N + n0 + tx * 8)     = *(float4*)&o[0];
        *(float4*)(C + (size_t)mrow * N + n0 + tx * 8 + 4) = *(float4*)&o[4];
    }
}

// ============================================================================
// Attention: 4 threads per query row (d-split into 16-float chunks).
// Block = 256 threads = 64 q rows, one (b,h).
// K/V tiles 32x64 in SMEM; mask int32 staged coalesced, packed to bitmask.
// Softmax without max-subtraction (scores O(6), exp(-1e9)==0 exactly).
// ============================================================================
__global__ __launch_bounds__(256) void attn_kernel(const int* __restrict__ mask)
{
    __shared__ float Ksm[32][DKH];   // 8 KB
    __shared__ float Vsm[32][DKH];   // 8 KB
    __shared__ int   Msm[64][33];    // 8.4 KB (+1 pad)

    const int tid  = threadIdx.x;
    const int half = tid & 3;            // d-chunk: 16 floats
    const int q    = tid >> 2;           // 0..63 local q row
    const int b    = blockIdx.z;
    const int h    = blockIdx.y;
    const int q0   = blockIdx.x * 64;
    const int qrow = q0 + q;
    const int dofs = half * 16;

    const float* qptr = g_q + (size_t)(b * SS + qrow) * DM + h * DKH + dofs;
    float qreg[16];
    #pragma unroll
    for (int d = 0; d < 16; d += 4)
        *(float4*)&qreg[d] = *(const float4*)(qptr + d);

    float acc[16];
    #pragma unroll
    for (int d = 0; d < 16; d++) acc[d] = 0.f;
    float lsum = 0.f;

    const float* kbase = g_k + (size_t)(b * SS) * DM + h * DKH;
    const float* vbase = g_v + (size_t)(b * SS) * DM + h * DKH;
    const int*   mbase = mask + (size_t)b * SS * SS;

    // K/V staging map: 32 rows x 64 floats = 512 float4; 256 threads x 2 float4
    const int lrow = tid >> 3;           // 0..31
    const int lc   = (tid & 7) * 8;      // 0..56 (2 consecutive float4)

    for (int k0 = 0; k0 < SS; k0 += 32) {
        __syncthreads();
        *(float4*)&Ksm[lrow][lc]     = *(const float4*)(kbase + (size_t)(k0 + lrow) * DM + lc);
        *(float4*)&Ksm[lrow][lc + 4] = *(const float4*)(kbase + (size_t)(k0 + lrow) * DM + lc + 4);
        *(float4*)&Vsm[lrow][lc]     = *(const float4*)(vbase + (size_t)(k0 + lrow) * DM + lc);
        *(float4*)&Vsm[lrow][lc + 4] = *(const float4*)(vbase + (size_t)(k0 + lrow) * DM + lc + 4);
        // mask tile: 64 rows x 32 ints = 2048 ints / 256 threads = 8 each
        #pragma unroll
        for (int i = 0; i < 8; i++) {
            int w   = i * 256 + tid;
            int row = w >> 5;
            int c   = w & 31;
            Msm[row][c] = mbase[(size_t)(q0 + row) * SS + k0 + c];
        }
        __syncthreads();

        unsigned int mbits = 0;
        #pragma unroll
        for (int j = 0; j < 32; j++)
            mbits |= (Msm[q][j] ? 1u : 0u) << j;

        #pragma unroll 4
        for (int j = 0; j < 32; j++) {
            const float4* k4 = (const float4*)&Ksm[j][dofs];
            float s = 0.f;
            #pragma unroll
            for (int d4 = 0; d4 < 4; d4++) {
                float4 kv = k4[d4];
                s += qreg[4*d4+0] * kv.x + qreg[4*d4+1] * kv.y
                   + qreg[4*d4+2] * kv.z + qreg[4*d4+3] * kv.w;
            }
            // combine partial dots across the 4 lanes of this q row
            s += __shfl_xor_sync(0xffffffffu, s, 1);
            s += __shfl_xor_sync(0xffffffffu, s, 2);
            s *= 0.125f;                              // 1/sqrt(64)
            if ((mbits >> j) & 1u) s = -1e9f;
            float p = __expf(s);                      // exp(-1e9) == 0 exactly
            lsum += p;
            const float4* v4 = (const float4*)&Vsm[j][dofs];
            #pragma unroll
            for (int d4 = 0; d4 < 4; d4++) {
                float4 vv = v4[d4];
                acc[4*d4+0] += p * vv.x;
                acc[4*d4+1] += p * vv.y;
                acc[4*d4+2] += p * vv.z;
                acc[4*d4+3] += p * vv.w;
            }
        }
    }

    float inv = 1.f / lsum;
    float* cp = g_ctx + (size_t)(b * SS + qrow) * DM + h * DKH + dofs;
    #pragma unroll
    for (int d = 0; d < 16; d += 4) {
        float4 o;
        o.x = acc[d]   * inv;
        o.y = acc[d+1] * inv;
        o.z = acc[d+2] * inv;
        o.w = acc[d+3] * inv;
        *(float4*)(cp + d) = o;
    }
}

// ============================================================================
// LayerNorm: 1 block per row, 256 threads, 3 elements each (768 = 256*3)
// ============================================================================
__global__ __launch_bounds__(256) void ln_kernel(
    const float* __restrict__ x,
    const float* __restrict__ gamma, const float* __restrict__ beta,
    float* __restrict__ out)
{
    const int row = blockIdx.x;
    const int tid = threadIdx.x;
    const float* xr = x + (size_t)row * DM;

    float v0 = xr[tid];
    float v1 = xr[tid + 256];
    float v2 = xr[tid + 512];
    float s  = v0 + v1 + v2;
    float sq = v0 * v0 + v1 * v1 + v2 * v2;

    #pragma unroll
    for (int o = 16; o > 0; o >>= 1) {
        s  += __shfl_xor_sync(0xffffffffu, s,  o);
        sq += __shfl_xor_sync(0xffffffffu, sq, o);
    }
    __shared__ float reds[8], redq[8];
    const int wid = tid >> 5, lid = tid & 31;
    if (lid == 0) { reds[wid] = s; redq[wid] = sq; }
    __syncthreads();
    float ts = 0.f, tq = 0.f;
    #pragma unroll
    for (int i = 0; i < 8; i++) { ts += reds[i]; tq += redq[i]; }

    const float mu  = ts * (1.f / DM);
    const float var = tq * (1.f / DM) - mu * mu;
    const float rs  = rsqrtf(var + 1e-5f);

    float* orow = out + (size_t)row * DM;
    orow[tid]       = (v0 - mu) * rs * gamma[tid]       + beta[tid];
    orow[tid + 256] = (v1 - mu) * rs * gamma[tid + 256] + beta[tid + 256];
    orow[tid + 512] = (v2 - mu) * rs * gamma[tid + 512] + beta[tid + 512];
}

// ============================================================================
// Launch
// ============================================================================
extern "C" void kernel_launch(void* const* d_in, const int* in_sizes, int n_in,
                              void* d_out, int out_size)
{
    const float* Qin  = (const float*)d_in[0];
    const float* Kin  = (const float*)d_in[1];
    const float* Vin  = (const float*)d_in[2];
    const int*   mask = (const int*)d_in[3];        // bool -> int32 0/1
    const float* Wq = (const float*)d_in[4];
    const float* bq = (const float*)d_in[5];
    const float* Wk = (const float*)d_in[6];
    const float* bk = (const float*)d_in[7];
    const float* Wv = (const float*)d_in[8];
    const float* bv = (const float*)d_in[9];
    const float* Wo = (const float*)d_in[10];
    const float* bo = (const float*)d_in[11];
    const float* gamma = (const float*)d_in[12];
    const float* beta  = (const float*)d_in[13];
    float* out = (float*)d_out;

    float *gq, *gk, *gv, *gctx, *gtmp;
    cudaGetSymbolAddress((void**)&gq,   g_q);
    cudaGetSymbolAddress((void**)&gk,   g_k);
    cudaGetSymbolAddress((void**)&gv,   g_v);
    cudaGetSymbolAddress((void**)&gctx, g_ctx);
    cudaGetSymbolAddress((void**)&gtmp, g_tmp);

    dim3 gemm_grid(DM / 128, M_TOT / 128);   // (6, 64)
    gemm_bias_kernel<false><<<gemm_grid, 256>>>(Qin, Wq, bq, nullptr, gq);
    gemm_bias_kernel<false><<<gemm_grid, 256>>>(Kin, Wk, bk, nullptr, gk);
    gemm_bias_kernel<false><<<gemm_grid, 256>>>(Vin, Wv, bv, nullptr, gv);

    attn_kernel<<<dim3(SS / 64, NH, BB), 256>>>(mask);

    gemm_bias_kernel<true><<<gemm_grid, 256>>>(gctx, Wo, bo, Qin, gtmp);

    ln_kernel<<<M_TOT, 256>>>(gtmp, gamma, beta, out);
}

// round 4
// speedup vs baseline: 2.1608x; 2.1608x over previous
#include <cuda_runtime.h>
#include <cuda_bf16.h>
#include <math.h>
#include <stdint.h>

#define BB     4
#define SS     2048
#define DM     768
#define NH     12
#define DKH    64
#define M_TOT  (BB*SS)   // 8192

// -------- scratch (static device arrays; no runtime allocation) --------
__device__ float g_q  [M_TOT*DM];
__device__ float g_k  [M_TOT*DM];
__device__ float g_v  [M_TOT*DM];
__device__ float g_ctx[M_TOT*DM];
__device__ float g_tmp[M_TOT*DM];

// ============================================================================
// Tensor-core helpers (mma.sync bf16 + ldmatrix)
// ============================================================================
__device__ __forceinline__ uint32_t smem_u32(const void* p) {
    return (uint32_t)__cvta_generic_to_shared(p);
}
__device__ __forceinline__ void ldsm4(uint32_t& r0, uint32_t& r1, uint32_t& r2, uint32_t& r3, uint32_t addr) {
    asm volatile("ldmatrix.sync.aligned.m8n8.x4.shared.b16 {%0,%1,%2,%3}, [%4];"
                 : "=r"(r0), "=r"(r1), "=r"(r2), "=r"(r3) : "r"(addr));
}
__device__ __forceinline__ void ldsm4t(uint32_t& r0, uint32_t& r1, uint32_t& r2, uint32_t& r3, uint32_t addr) {
    asm volatile("ldmatrix.sync.aligned.m8n8.x4.trans.shared.b16 {%0,%1,%2,%3}, [%4];"
                 : "=r"(r0), "=r"(r1), "=r"(r2), "=r"(r3) : "r"(addr));
}
__device__ __forceinline__ void mma_bf16(float* c, uint32_t a0, uint32_t a1, uint32_t a2, uint32_t a3,
                                         uint32_t b0, uint32_t b1) {
    asm volatile("mma.sync.aligned.m16n8k16.row.col.f32.bf16.bf16.f32 "
                 "{%0,%1,%2,%3},{%4,%5,%6,%7},{%8,%9},{%0,%1,%2,%3};"
                 : "+f"(c[0]), "+f"(c[1]), "+f"(c[2]), "+f"(c[3])
                 : "r"(a0), "r"(a1), "r"(a2), "r"(a3), "r"(b0), "r"(b1));
}

// ============================================================================
// Tensor-core GEMM: C[M,768] = A[M,768] @ W[768,768] + bias (+ residual)
// bf16 3-term split (hi*hi + hi*lo + lo*hi) for ~fp32 accuracy.
// 128x128 tile, BK=16, 256 threads = 8 warps (2m x 4n), warp tile 64x32.
// ============================================================================
#define AST 24    // A smem row stride in bf16 (48 B)  -> bank-disjoint ldsm
#define BST 136   // B smem row stride in bf16 (272 B) -> bank-disjoint ldsm.trans

template<bool RESID>
__global__ __launch_bounds__(256) void gemm_tc_kernel(
    const float* __restrict__ A, const float* __restrict__ W,
    const float* __restrict__ bias, const float* __restrict__ resid,
    float* __restrict__ C)
{
    const int N = DM, K = DM;
    __shared__ __nv_bfloat16 Ah[128 * AST];
    __shared__ __nv_bfloat16 Al[128 * AST];
    __shared__ __nv_bfloat16 Bh[16 * BST];
    __shared__ __nv_bfloat16 Bl[16 * BST];

    const int tid  = threadIdx.x;
    const int wid  = tid >> 5;
    const int lane = tid & 31;
    const int m0   = blockIdx.y * 128;
    const int n0   = blockIdx.x * 128;

    const int warp_m = (wid & 1) * 64;   // 0 or 64
    const int warp_n = (wid >> 1) * 32;  // 0,32,64,96

    // staging maps
    const int sar = tid >> 1;            // A row 0..127
    const int sac = (tid & 1) * 8;       // A col 0 or 8
    const int sbr = tid >> 4;            // B (k) row 0..15
    const int sbc = (tid & 15) * 8;      // B (n) col 0..120

    // ldmatrix lane addressing
    const int lrow = lane & 7;
    const int lsel = lane >> 3;          // 0..3
    const int arow_f = lrow + ((lsel & 1) ? 8 : 0);
    const int akb    = (lsel & 2) ? 16 : 0;            // byte offset (k half)
    const int bkr    = lrow + ((lsel & 1) ? 8 : 0);    // k row for B
    const int bn_sub = (lsel & 2) ? 8 : 0;             // second ntile of pair

    const uint32_t ah_base = smem_u32(Ah);
    const uint32_t al_base = smem_u32(Al);
    const uint32_t bh_base = smem_u32(Bh);
    const uint32_t bl_base = smem_u32(Bl);

    float acc[4][4][4] = {};

    for (int k0 = 0; k0 < K; k0 += 16) {
        // ---- stage A tile 128x16 (split hi/lo) ----
        {
            const float* ap = A + (size_t)(m0 + sar) * K + k0 + sac;
            float4 v0 = *(const float4*)(ap);
            float4 v1 = *(const float4*)(ap + 4);
            float vv[8] = {v0.x, v0.y, v0.z, v0.w, v1.x, v1.y, v1.z, v1.w};
            #pragma unroll
            for (int i = 0; i < 4; i++) {
                float x = vv[2*i], y = vv[2*i+1];
                __nv_bfloat16 hx = __float2bfloat16(x);
                __nv_bfloat16 hy = __float2bfloat16(y);
                __nv_bfloat16 lx = __float2bfloat16(x - __bfloat162float(hx));
                __nv_bfloat16 ly = __float2bfloat16(y - __bfloat162float(hy));
                __nv_bfloat162 hp; hp.x = hx; hp.y = hy;
                __nv_bfloat162 lp; lp.x = lx; lp.y = ly;
                *(__nv_bfloat162*)&Ah[sar * AST + sac + 2*i] = hp;
                *(__nv_bfloat162*)&Al[sar * AST + sac + 2*i] = lp;
            }
        }
        // ---- stage B tile 16x128 (k-major, split hi/lo) ----
        {
            const float* wp = W + (size_t)(k0 + sbr) * N + n0 + sbc;
            float4 v0 = *(const float4*)(wp);
            float4 v1 = *(const float4*)(wp + 4);
            float vv[8] = {v0.x, v0.y, v0.z, v0.w, v1.x, v1.y, v1.z, v1.w};
            #pragma unroll
            for (int i = 0; i < 4; i++) {
                float x = vv[2*i], y = vv[2*i+1];
                __nv_bfloat16 hx = __float2bfloat16(x);
                __nv_bfloat16 hy = __float2bfloat16(y);
                __nv_bfloat16 lx = __float2bfloat16(x - __bfloat162float(hx));
                __nv_bfloat16 ly = __float2bfloat16(y - __bfloat162float(hy));
                __nv_bfloat162 hp; hp.x = hx; hp.y = hy;
                __nv_bfloat162 lp; lp.x = lx; lp.y = ly;
                *(__nv_bfloat162*)&Bh[sbr * BST + sbc + 2*i] = hp;
                *(__nv_bfloat162*)&Bl[sbr * BST + sbc + 2*i] = lp;
            }
        }
        __syncthreads();

        // ---- load fragments ----
        uint32_t ahf[4][4], alf[4][4];
        #pragma unroll
        for (int t = 0; t < 4; t++) {
            uint32_t off = (uint32_t)((warp_m + t*16 + arow_f) * AST * 2 + akb);
            ldsm4(ahf[t][0], ahf[t][1], ahf[t][2], ahf[t][3], ah_base + off);
            ldsm4(alf[t][0], alf[t][1], alf[t][2], alf[t][3], al_base + off);
        }
        uint32_t bhf[4][2], blf[4][2];
        #pragma unroll
        for (int u = 0; u < 2; u++) {
            uint32_t off = (uint32_t)(bkr * BST * 2 + (warp_n + u*16 + bn_sub) * 2);
            uint32_t r0, r1, r2, r3;
            ldsm4t(r0, r1, r2, r3, bh_base + off);
            bhf[u*2][0] = r0; bhf[u*2][1] = r1; bhf[u*2+1][0] = r2; bhf[u*2+1][1] = r3;
            ldsm4t(r0, r1, r2, r3, bl_base + off);
            blf[u*2][0] = r0; blf[u*2][1] = r1; blf[u*2+1][0] = r2; blf[u*2+1][1] = r3;
        }

        // ---- mma: hi*hi + hi*lo + lo*hi ----
        #pragma unroll
        for (int t = 0; t < 4; t++) {
            #pragma unroll
            for (int n = 0; n < 4; n++) {
                mma_bf16(acc[t][n], ahf[t][0], ahf[t][1], ahf[t][2], ahf[t][3], bhf[n][0], bhf[n][1]);
                mma_bf16(acc[t][n], ahf[t][0], ahf[t][1], ahf[t][2], ahf[t][3], blf[n][0], blf[n][1]);
                mma_bf16(acc[t][n], alf[t][0], alf[t][1], alf[t][2], alf[t][3], bhf[n][0], bhf[n][1]);
            }
        }
        __syncthreads();
    }

    // ---- epilogue ----
    const int g   = lane >> 2;
    const int tig = lane & 3;
    #pragma unroll
    for (int t = 0; t < 4; t++) {
        #pragma unroll
        for (int n = 0; n < 4; n++) {
            int row0 = m0 + warp_m + t*16 + g;
            int row1 = row0 + 8;
            int col  = n0 + warp_n + n*8 + tig*2;
            float2 bi = *(const float2*)(bias + col);
            float2 o0, o1;
            o0.x = acc[t][n][0] + bi.x;  o0.y = acc[t][n][1] + bi.y;
            o1.x = acc[t][n][2] + bi.x;  o1.y = acc[t][n][3] + bi.y;
            if (RESID) {
                float2 r0 = *(const float2*)(resid + (size_t)row0 * N + col);
                float2 r1 = *(const float2*)(resid + (size_t)row1 * N + col);
                o0.x += r0.x; o0.y += r0.y;
                o1.x += r1.x; o1.y += r1.y;
            }
            *(float2*)(C + (size_t)row0 * N + col) = o0;
            *(float2*)(C + (size_t)row1 * N + col) = o1;
        }
    }
}

// ============================================================================
// Attention (R2 version): 1 thread = 1 query row. Block = 128 q rows.
// K/V tiles 32x64 in SMEM with broadcast float4 reads (1 wavefront/LDS.128).
// Softmax without max-subtraction; masked -> exp(-1e9) == 0 exactly.
// ============================================================================
__global__ __launch_bounds__(128) void attn_kernel(const int* __restrict__ mask)
{
    __shared__ float Ksm[32][DKH];   // 8 KB
    __shared__ float Vsm[32][DKH];   // 8 KB
    __shared__ int   Msm[128][33];   // ~16.9 KB (+1 pad)

    const int tid  = threadIdx.x;
    const int b    = blockIdx.z;
    const int h    = blockIdx.y;
    const int q0   = blockIdx.x * 128;
    const int qrow = q0 + tid;

    const float* qptr = g_q + (size_t)(b * SS + qrow) * DM + h * DKH;
    float qreg[DKH];
    #pragma unroll
    for (int d = 0; d < DKH; d += 4)
        *(float4*)&qreg[d] = *(const float4*)(qptr + d);

    float acc[DKH];
    #pragma unroll
    for (int d = 0; d < DKH; d++) acc[d] = 0.f;
    float lsum = 0.f;

    const float* kbase = g_k + (size_t)(b * SS) * DM + h * DKH;
    const float* vbase = g_v + (size_t)(b * SS) * DM + h * DKH;
    const int*   mbase = mask + (size_t)b * SS * SS;

    const int lrow = tid >> 2;          // 0..31
    const int lc   = (tid & 3) * 16;    // 16 floats per loader

    for (int k0 = 0; k0 < SS; k0 += 32) {
        __syncthreads();
        #pragma unroll
        for (int i = 0; i < 4; i++) {
            int col = lc + i * 4;
            *(float4*)&Ksm[lrow][col] = *(const float4*)(kbase + (size_t)(k0 + lrow) * DM + col);
            *(float4*)&Vsm[lrow][col] = *(const float4*)(vbase + (size_t)(k0 + lrow) * DM + col);
        }
        #pragma unroll
        for (int i = 0; i < 32; i++) {
            int w   = i * 128 + tid;
            int row = w >> 5;
            int c   = w & 31;
            Msm[row][c] = mbase[(size_t)(q0 + row) * SS + k0 + c];
        }
        __syncthreads();

        unsigned int mbits = 0;
        #pragma unroll
        for (int j = 0; j < 32; j++)
            mbits |= (Msm[tid][j] ? 1u : 0u) << j;

        #pragma unroll
        for (int j = 0; j < 32; j++) {
            const float4* k4 = (const float4*)&Ksm[j][0];
            float s = 0.f;
            #pragma unroll
            for (int d4 = 0; d4 < 16; d4++) {
                float4 kv = k4[d4];
                s += qreg[4*d4+0] * kv.x + qreg[4*d4+1] * kv.y
                   + qreg[4*d4+2] * kv.z + qreg[4*d4+3] * kv.w;
            }
            s *= 0.125f;
            if ((mbits >> j) & 1u) s = -1e9f;
            float p = __expf(s);
            lsum += p;
            const float4* v4 = (const float4*)&Vsm[j][0];
            #pragma unroll
            for (int d4 = 0; d4 < 16; d4++) {
                float4 vv = v4[d4];
                acc[4*d4+0] += p * vv.x;
                acc[4*d4+1] += p * vv.y;
                acc[4*d4+2] += p * vv.z;
                acc[4*d4+3] += p * vv.w;
            }
        }
    }

    float inv = 1.f / lsum;
    float* cp = g_ctx + (size_t)(b * SS + qrow) * DM + h * DKH;
    #pragma unroll
    for (int d = 0; d < DKH; d += 4) {
        float4 o;
        o.x = acc[d]   * inv;
        o.y = acc[d+1] * inv;
        o.z = acc[d+2] * inv;
        o.w = acc[d+3] * inv;
        *(float4*)(cp + d) = o;
    }
}

// ============================================================================
// LayerNorm: 1 block per row, 256 threads, 3 elements each
// ============================================================================
__global__ __launch_bounds__(256) void ln_kernel(
    const float* __restrict__ x,
    const float* __restrict__ gamma, const float* __restrict__ beta,
    float* __restrict__ out)
{
    const int row = blockIdx.x;
    const int tid = threadIdx.x;
    const float* xr = x + (size_t)row * DM;

    float v0 = xr[tid];
    float v1 = xr[tid + 256];
    float v2 = xr[tid + 512];
    float s  = v0 + v1 + v2;
    float sq = v0 * v0 + v1 * v1 + v2 * v2;

    #pragma unroll
    for (int o = 16; o > 0; o >>= 1) {
        s  += __shfl_xor_sync(0xffffffffu, s,  o);
        sq += __shfl_xor_sync(0xffffffffu, sq, o);
    }
    __shared__ float reds[8], redq[8];
    const int wid = tid >> 5, lid = tid & 31;
    if (lid == 0) { reds[wid] = s; redq[wid] = sq; }
    __syncthreads();
    float ts = 0.f, tq = 0.f;
    #pragma unroll
    for (int i = 0; i < 8; i++) { ts += reds[i]; tq += redq[i]; }

    const float mu  = ts * (1.f / DM);
    const float var = tq * (1.f / DM) - mu * mu;
    const float rs  = rsqrtf(var + 1e-5f);

    float* orow = out + (size_t)row * DM;
    orow[tid]       = (v0 - mu) * rs * gamma[tid]       + beta[tid];
    orow[tid + 256] = (v1 - mu) * rs * gamma[tid + 256] + beta[tid + 256];
    orow[tid + 512] = (v2 - mu) * rs * gamma[tid + 512] + beta[tid + 512];
}

// ============================================================================
// Launch
// ============================================================================
extern "C" void kernel_launch(void* const* d_in, const int* in_sizes, int n_in,
                              void* d_out, int out_size)
{
    const float* Qin  = (const float*)d_in[0];
    const float* Kin  = (const float*)d_in[1];
    const float* Vin  = (const float*)d_in[2];
    const int*   mask = (const int*)d_in[3];        // bool -> int32 0/1
    const float* Wq = (const float*)d_in[4];
    const float* bq = (const float*)d_in[5];
    const float* Wk = (const float*)d_in[6];
    const float* bk = (const float*)d_in[7];
    const float* Wv = (const float*)d_in[8];
    const float* bv = (const float*)d_in[9];
    const float* Wo = (const float*)d_in[10];
    const float* bo = (const float*)d_in[11];
    const float* gamma = (const float*)d_in[12];
    const float* beta  = (const float*)d_in[13];
    float* out = (float*)d_out;

    float *gq, *gk, *gv, *gctx, *gtmp;
    cudaGetSymbolAddress((void**)&gq,   g_q);
    cudaGetSymbolAddress((void**)&gk,   g_k);
    cudaGetSymbolAddress((void**)&gv,   g_v);
    cudaGetSymbolAddress((void**)&gctx, g_ctx);
    cudaGetSymbolAddress((void**)&gtmp, g_tmp);

    dim3 gemm_grid(DM / 128, M_TOT / 128);   // (6, 64)
    gemm_tc_kernel<false><<<gemm_grid, 256>>>(Qin, Wq, bq, nullptr, gq);
    gemm_tc_kernel<false><<<gemm_grid, 256>>>(Kin, Wk, bk, nullptr, gk);
    gemm_tc_kernel<false><<<gemm_grid, 256>>>(Vin, Wv, bv, nullptr, gv);

    attn_kernel<<<dim3(SS / 128, NH, BB), 128>>>(mask);

    gemm_tc_kernel<true><<<gemm_grid, 256>>>(gctx, Wo, bo, Qin, gtmp);

    ln_kernel<<<M_TOT, 256>>>(gtmp, gamma, beta, out);
}

// round 5
// speedup vs baseline: 7.8567x; 3.6360x over previous
#include <cuda_runtime.h>
#include <cuda_bf16.h>
#include <math.h>
#include <stdint.h>

#define BB     4
#define SS     2048
#define DM     768
#define NH     12
#define DKH    64
#define M_TOT  (BB*SS)   // 8192

// -------- scratch (static device arrays; no runtime allocation) --------
__device__ float g_q  [M_TOT*DM];
__device__ float g_k  [M_TOT*DM];
__device__ float g_v  [M_TOT*DM];
__device__ float g_ctx[M_TOT*DM];
__device__ float g_tmp[M_TOT*DM];
__device__ uint32_t g_mbits[BB*SS*(SS/32)];   // 2 MB packed mask bits

// ============================================================================
// Tensor-core helpers (mma.sync bf16 + ldmatrix)
// ============================================================================
__device__ __forceinline__ uint32_t smem_u32(const void* p) {
    return (uint32_t)__cvta_generic_to_shared(p);
}
__device__ __forceinline__ void ldsm4(uint32_t& r0, uint32_t& r1, uint32_t& r2, uint32_t& r3, uint32_t addr) {
    asm volatile("ldmatrix.sync.aligned.m8n8.x4.shared.b16 {%0,%1,%2,%3}, [%4];"
                 : "=r"(r0), "=r"(r1), "=r"(r2), "=r"(r3) : "r"(addr));
}
__device__ __forceinline__ void ldsm4t(uint32_t& r0, uint32_t& r1, uint32_t& r2, uint32_t& r3, uint32_t addr) {
    asm volatile("ldmatrix.sync.aligned.m8n8.x4.trans.shared.b16 {%0,%1,%2,%3}, [%4];"
                 : "=r"(r0), "=r"(r1), "=r"(r2), "=r"(r3) : "r"(addr));
}
__device__ __forceinline__ void mma_bf16(float* c, uint32_t a0, uint32_t a1, uint32_t a2, uint32_t a3,
                                         uint32_t b0, uint32_t b1) {
    asm volatile("mma.sync.aligned.m16n8k16.row.col.f32.bf16.bf16.f32 "
                 "{%0,%1,%2,%3},{%4,%5,%6,%7},{%8,%9},{%0,%1,%2,%3};"
                 : "+f"(c[0]), "+f"(c[1]), "+f"(c[2]), "+f"(c[3])
                 : "r"(a0), "r"(a1), "r"(a2), "r"(a3), "r"(b0), "r"(b1));
}
__device__ __forceinline__ uint32_t pack_bf16(float x, float y) {
    __nv_bfloat162 p;
    p.x = __float2bfloat16(x);
    p.y = __float2bfloat16(y);
    return *(uint32_t*)&p;
}

// ============================================================================
// Mask pack: int32 0/1 -> bit per key.  word[(b*S+q)*64 + k/32], bit k%32.
// ============================================================================
__global__ __launch_bounds__(256) void mask_pack_kernel(const int* __restrict__ mask,
                                                        uint32_t* __restrict__ bits)
{
    const int warp = (blockIdx.x * blockDim.x + threadIdx.x) >> 5;
    const int lane = threadIdx.x & 31;
    const size_t base = (size_t)warp * 16 * 32;
    #pragma unroll
    for (int i = 0; i < 16; i++) {
        int v = mask[base + i * 32 + lane];
        unsigned bal = __ballot_sync(0xffffffffu, v != 0);
        if (lane == 0) bits[warp * 16 + i] = bal;
    }
}

// ============================================================================
// Tensor-core GEMM: C[M,768] = A[M,768] @ W[768,768] + bias (+ residual)
// bf16 3-term split (hi*hi + hi*lo + lo*hi). 128x128 tile, BK=16, 8 warps.
// ============================================================================
#define AST 24
#define BST 136

template<bool RESID>
__global__ __launch_bounds__(256) void gemm_tc_kernel(
    const float* __restrict__ A, const float* __restrict__ W,
    const float* __restrict__ bias, const float* __restrict__ resid,
    float* __restrict__ C)
{
    const int N = DM, K = DM;
    __shared__ __nv_bfloat16 Ah[128 * AST];
    __shared__ __nv_bfloat16 Al[128 * AST];
    __shared__ __nv_bfloat16 Bh[16 * BST];
    __shared__ __nv_bfloat16 Bl[16 * BST];

    const int tid  = threadIdx.x;
    const int wid  = tid >> 5;
    const int lane = tid & 31;
    const int m0   = blockIdx.y * 128;
    const int n0   = blockIdx.x * 128;

    const int warp_m = (wid & 1) * 64;
    const int warp_n = (wid >> 1) * 32;

    const int sar = tid >> 1;
    const int sac = (tid & 1) * 8;
    const int sbr = tid >> 4;
    const int sbc = (tid & 15) * 8;

    const int lrow = lane & 7;
    const int lsel = lane >> 3;
    const int arow_f = lrow + ((lsel & 1) ? 8 : 0);
    const int akb    = (lsel & 2) ? 16 : 0;
    const int bkr    = lrow + ((lsel & 1) ? 8 : 0);
    const int bn_sub = (lsel & 2) ? 8 : 0;

    const uint32_t ah_base = smem_u32(Ah);
    const uint32_t al_base = smem_u32(Al);
    const uint32_t bh_base = smem_u32(Bh);
    const uint32_t bl_base = smem_u32(Bl);

    float acc[4][4][4] = {};

    for (int k0 = 0; k0 < K; k0 += 16) {
        {
            const float* ap = A + (size_t)(m0 + sar) * K + k0 + sac;
            float4 v0 = *(const float4*)(ap);
            float4 v1 = *(const float4*)(ap + 4);
            float vv[8] = {v0.x, v0.y, v0.z, v0.w, v1.x, v1.y, v1.z, v1.w};
            #pragma unroll
            for (int i = 0; i < 4; i++) {
                float x = vv[2*i], y = vv[2*i+1];
                __nv_bfloat16 hx = __float2bfloat16(x);
                __nv_bfloat16 hy = __float2bfloat16(y);
                __nv_bfloat16 lx = __float2bfloat16(x - __bfloat162float(hx));
                __nv_bfloat16 ly = __float2bfloat16(y - __bfloat162float(hy));
                __nv_bfloat162 hp; hp.x = hx; hp.y = hy;
                __nv_bfloat162 lp; lp.x = lx; lp.y = ly;
                *(__nv_bfloat162*)&Ah[sar * AST + sac + 2*i] = hp;
                *(__nv_bfloat162*)&Al[sar * AST + sac + 2*i] = lp;
            }
        }
        {
            const float* wp = W + (size_t)(k0 + sbr) * N + n0 + sbc;
            float4 v0 = *(const float4*)(wp);
            float4 v1 = *(const float4*)(wp + 4);
            float vv[8] = {v0.x, v0.y, v0.z, v0.w, v1.x, v1.y, v1.z, v1.w};
            #pragma unroll
            for (int i = 0; i < 4; i++) {
                float x = vv[2*i], y = vv[2*i+1];
                __nv_bfloat16 hx = __float2bfloat16(x);
                __nv_bfloat16 hy = __float2bfloat16(y);
                __nv_bfloat16 lx = __float2bfloat16(x - __bfloat162float(hx));
                __nv_bfloat16 ly = __float2bfloat16(y - __bfloat162float(hy));
                __nv_bfloat162 hp; hp.x = hx; hp.y = hy;
                __nv_bfloat162 lp; lp.x = lx; lp.y = ly;
                *(__nv_bfloat162*)&Bh[sbr * BST + sbc + 2*i] = hp;
                *(__nv_bfloat162*)&Bl[sbr * BST + sbc + 2*i] = lp;
            }
        }
        __syncthreads();

        uint32_t ahf[4][4], alf[4][4];
        #pragma unroll
        for (int t = 0; t < 4; t++) {
            uint32_t off = (uint32_t)((warp_m + t*16 + arow_f) * AST * 2 + akb);
            ldsm4(ahf[t][0], ahf[t][1], ahf[t][2], ahf[t][3], ah_base + off);
            ldsm4(alf[t][0], alf[t][1], alf[t][2], alf[t][3], al_base + off);
        }
        uint32_t bhf[4][2], blf[4][2];
        #pragma unroll
        for (int u = 0; u < 2; u++) {
            uint32_t off = (uint32_t)(bkr * BST * 2 + (warp_n + u*16 + bn_sub) * 2);
            uint32_t r0, r1, r2, r3;
            ldsm4t(r0, r1, r2, r3, bh_base + off);
            bhf[u*2][0] = r0; bhf[u*2][1] = r1; bhf[u*2+1][0] = r2; bhf[u*2+1][1] = r3;
            ldsm4t(r0, r1, r2, r3, bl_base + off);
            blf[u*2][0] = r0; blf[u*2][1] = r1; blf[u*2+1][0] = r2; blf[u*2+1][1] = r3;
        }

        #pragma unroll
        for (int t = 0; t < 4; t++) {
            #pragma unroll
            for (int n = 0; n < 4; n++) {
                mma_bf16(acc[t][n], ahf[t][0], ahf[t][1], ahf[t][2], ahf[t][3], bhf[n][0], bhf[n][1]);
                mma_bf16(acc[t][n], ahf[t][0], ahf[t][1], ahf[t][2], ahf[t][3], blf[n][0], blf[n][1]);
                mma_bf16(acc[t][n], alf[t][0], alf[t][1], alf[t][2], alf[t][3], bhf[n][0], bhf[n][1]);
            }
        }
        __syncthreads();
    }

    const int g   = lane >> 2;
    const int tig = lane & 3;
    #pragma unroll
    for (int t = 0; t < 4; t++) {
        #pragma unroll
        for (int n = 0; n < 4; n++) {
            int row0 = m0 + warp_m + t*16 + g;
            int row1 = row0 + 8;
            int col  = n0 + warp_n + n*8 + tig*2;
            float2 bi = *(const float2*)(bias + col);
            float2 o0, o1;
            o0.x = acc[t][n][0] + bi.x;  o0.y = acc[t][n][1] + bi.y;
            o1.x = acc[t][n][2] + bi.x;  o1.y = acc[t][n][3] + bi.y;
            if (RESID) {
                float2 r0 = *(const float2*)(resid + (size_t)row0 * N + col);
                float2 r1 = *(const float2*)(resid + (size_t)row1 * N + col);
                o0.x += r0.x; o0.y += r0.y;
                o1.x += r1.x; o1.y += r1.y;
            }
            *(float2*)(C + (size_t)row0 * N + col) = o0;
            *(float2*)(C + (size_t)row1 * N + col) = o1;
        }
    }
}

// ============================================================================
// Tensor-core flash attention.
// CTA: 128 q rows x one (b,h). 8 warps, each 16 q rows.
// Key loop: 64-key tiles. K,V staged fp32->bf16 in SMEM (stride 72 -> ldmatrix
// conflict-free). QK^T and PV via mma.sync m16n8k16. Softmax w/o max-sub.
// ============================================================================
#define KST 72

__global__ __launch_bounds__(256, 2) void attn_tc_kernel(const uint32_t* __restrict__ mbits)
{
    __shared__ __nv_bfloat16 s_buf[2 * 64 * KST];   // 18.4 KB; Q stage overlays K+V
    __nv_bfloat16* Ks = s_buf;
    __nv_bfloat16* Vs = s_buf + 64 * KST;

    const int tid  = threadIdx.x;
    const int wid  = tid >> 5;
    const int lane = tid & 31;
    const int b    = blockIdx.z;
    const int h    = blockIdx.y;
    const int q0   = blockIdx.x * 128;
    const int g    = lane >> 2;
    const int t4   = lane & 3;

    // ---- stage Q tile [128 x 64] fp32 -> bf16 smem [128][KST] ----
    {
        const int r  = tid >> 1;
        const int hh = (tid & 1) * 32;
        const float* qp = g_q + (size_t)(b * SS + q0 + r) * DM + h * DKH + hh;
        __nv_bfloat16* dst = s_buf + r * KST + hh;
        #pragma unroll
        for (int i = 0; i < 8; i++) {
            float4 v = *(const float4*)(qp + i * 4);
            dst[i*4+0] = __float2bfloat16(v.x);
            dst[i*4+1] = __float2bfloat16(v.y);
            dst[i*4+2] = __float2bfloat16(v.z);
            dst[i*4+3] = __float2bfloat16(v.w);
        }
    }
    __syncthreads();

    // ---- Q fragments (constant over key loop) ----
    uint32_t qa[4][4];
    {
        const uint32_t base = smem_u32(s_buf);
        const int row  = wid * 16 + (lane & 15);
        const int colh = (lane >> 4) * 8;
        #pragma unroll
        for (int j = 0; j < 4; j++)
            ldsm4(qa[j][0], qa[j][1], qa[j][2], qa[j][3],
                  base + (uint32_t)((row * KST + j * 16 + colh) * 2));
    }

    float o[8][4] = {};
    float ls0 = 0.f, ls1 = 0.f;

    const float* kg = g_k + (size_t)(b * SS) * DM + h * DKH;
    const float* vg = g_v + (size_t)(b * SS) * DM + h * DKH;
    const uint32_t* mrow0 = mbits + ((size_t)(b * SS + q0 + wid * 16 + g)) * (SS/32);
    const uint32_t* mrow1 = mrow0 + 8 * (SS/32);

    const uint32_t ks_base = smem_u32(Ks);
    const uint32_t vs_base = smem_u32(Vs);

    // ldmatrix per-lane offsets
    const int krow = (lane & 7) + ((lane >> 4) ? 8 : 0);       // K: n(keys) rows
    const int kcol = ((lane >> 3) & 1) * 8;                    // K: d col half
    const int vrow = (lane & 7) + (((lane >> 3) & 1) ? 8 : 0); // V: k(keys) rows
    const int vcol = (lane >> 4) * 8;                          // V: d col half
    const uint32_t kaddr0 = ks_base + (uint32_t)((krow * KST + kcol) * 2);
    const uint32_t vaddr0 = vs_base + (uint32_t)((vrow * KST + vcol) * 2);

    const int srow = tid >> 2;         // staging row 0..63
    const int scol = (tid & 3) * 16;   // staging col base

    for (int k0 = 0; k0 < SS; k0 += 64) {
        __syncthreads();
        // ---- stage K,V tiles [64 x 64] fp32 -> bf16 ----
        {
            const float* kp = kg + (size_t)(k0 + srow) * DM + scol;
            const float* vp = vg + (size_t)(k0 + srow) * DM + scol;
            __nv_bfloat16* kd = Ks + srow * KST + scol;
            __nv_bfloat16* vd = Vs + srow * KST + scol;
            #pragma unroll
            for (int i = 0; i < 4; i++) {
                float4 kv = *(const float4*)(kp + i * 4);
                kd[i*4+0] = __float2bfloat16(kv.x);
                kd[i*4+1] = __float2bfloat16(kv.y);
                kd[i*4+2] = __float2bfloat16(kv.z);
                kd[i*4+3] = __float2bfloat16(kv.w);
                float4 vv = *(const float4*)(vp + i * 4);
                vd[i*4+0] = __float2bfloat16(vv.x);
                vd[i*4+1] = __float2bfloat16(vv.y);
                vd[i*4+2] = __float2bfloat16(vv.z);
                vd[i*4+3] = __float2bfloat16(vv.w);
            }
        }
        __syncthreads();

        // ---- S = Q K^T  (16 x 64 per warp) ----
        float c[8][4] = {};
        #pragma unroll
        for (int np = 0; np < 4; np++) {
            #pragma unroll
            for (int j = 0; j < 4; j++) {
                uint32_t r0, r1, r2, r3;
                ldsm4(r0, r1, r2, r3, kaddr0 + (uint32_t)((np*16*KST + j*16) * 2));
                mma_bf16(c[2*np],   qa[j][0], qa[j][1], qa[j][2], qa[j][3], r0, r1);
                mma_bf16(c[2*np+1], qa[j][0], qa[j][1], qa[j][2], qa[j][3], r2, r3);
            }
        }

        // ---- mask + exp + row-sum ----
        const int kw = k0 >> 5;
        const uint32_t m0a = mrow0[kw], m0b = mrow0[kw+1];
        const uint32_t m1a = mrow1[kw], m1b = mrow1[kw+1];
        #pragma unroll
        for (int nt = 0; nt < 8; nt++) {
            const int colb = nt * 8 + 2 * t4;       // even, 0..62
            const uint32_t w0 = (colb & 32) ? m0b : m0a;
            const uint32_t w1 = (colb & 32) ? m1b : m1a;
            const int bit = colb & 31;
            float p0 = ((w0 >> bit)     & 1u) ? 0.f : __expf(c[nt][0] * 0.125f);
            float p1 = ((w0 >> (bit+1)) & 1u) ? 0.f : __expf(c[nt][1] * 0.125f);
            float p2 = ((w1 >> bit)     & 1u) ? 0.f : __expf(c[nt][2] * 0.125f);
            float p3 = ((w1 >> (bit+1)) & 1u) ? 0.f : __expf(c[nt][3] * 0.125f);
            ls0 += p0 + p1;
            ls1 += p2 + p3;
            c[nt][0] = p0; c[nt][1] = p1; c[nt][2] = p2; c[nt][3] = p3;
        }

        // ---- repack P (C-frag -> A-frag, FA2 identity) ----
        uint32_t pa[4][4];
        #pragma unroll
        for (int j = 0; j < 4; j++) {
            pa[j][0] = pack_bf16(c[2*j][0],   c[2*j][1]);
            pa[j][1] = pack_bf16(c[2*j][2],   c[2*j][3]);
            pa[j][2] = pack_bf16(c[2*j+1][0], c[2*j+1][1]);
            pa[j][3] = pack_bf16(c[2*j+1][2], c[2*j+1][3]);
        }

        // ---- O += P V ----
        #pragma unroll
        for (int np = 0; np < 4; np++) {
            #pragma unroll
            for (int j = 0; j < 4; j++) {
                uint32_t r0, r1, r2, r3;
                ldsm4t(r0, r1, r2, r3, vaddr0 + (uint32_t)((j*16*KST + np*16) * 2));
                mma_bf16(o[2*np],   pa[j][0], pa[j][1], pa[j][2], pa[j][3], r0, r1);
                mma_bf16(o[2*np+1], pa[j][0], pa[j][1], pa[j][2], pa[j][3], r2, r3);
            }
        }
    }

    // ---- final row-sum reduction across the quad, normalize, store ----
    ls0 += __shfl_xor_sync(0xffffffffu, ls0, 1);
    ls0 += __shfl_xor_sync(0xffffffffu, ls0, 2);
    ls1 += __shfl_xor_sync(0xffffffffu, ls1, 1);
    ls1 += __shfl_xor_sync(0xffffffffu, ls1, 2);
    const float inv0 = 1.f / ls0;
    const float inv1 = 1.f / ls1;

    float* cp0 = g_ctx + (size_t)(b * SS + q0 + wid * 16 + g) * DM + h * DKH;
    float* cp1 = cp0 + 8 * DM;
    #pragma unroll
    for (int nt = 0; nt < 8; nt++) {
        const int col = nt * 8 + 2 * t4;
        float2 a, bb2;
        a.x   = o[nt][0] * inv0;  a.y   = o[nt][1] * inv0;
        bb2.x = o[nt][2] * inv1;  bb2.y = o[nt][3] * inv1;
        *(float2*)(cp0 + col) = a;
        *(float2*)(cp1 + col) = bb2;
    }
}

// ============================================================================
// LayerNorm: 1 block per row, 256 threads, 3 elements each
// ============================================================================
__global__ __launch_bounds__(256) void ln_kernel(
    const float* __restrict__ x,
    const float* __restrict__ gamma, const float* __restrict__ beta,
    float* __restrict__ out)
{
    const int row = blockIdx.x;
    const int tid = threadIdx.x;
    const float* xr = x + (size_t)row * DM;

    float v0 = xr[tid];
    float v1 = xr[tid + 256];
    float v2 = xr[tid + 512];
    float s  = v0 + v1 + v2;
    float sq = v0 * v0 + v1 * v1 + v2 * v2;

    #pragma unroll
    for (int o = 16; o > 0; o >>= 1) {
        s  += __shfl_xor_sync(0xffffffffu, s,  o);
        sq += __shfl_xor_sync(0xffffffffu, sq, o);
    }
    __shared__ float reds[8], redq[8];
    const int wid = tid >> 5, lid = tid & 31;
    if (lid == 0) { reds[wid] = s; redq[wid] = sq; }
    __syncthreads();
    float ts = 0.f, tq = 0.f;
    #pragma unroll
    for (int i = 0; i < 8; i++) { ts += reds[i]; tq += redq[i]; }

    const float mu  = ts * (1.f / DM);
    const float var = tq * (1.f / DM) - mu * mu;
    const float rs  = rsqrtf(var + 1e-5f);

    float* orow = out + (size_t)row * DM;
    orow[tid]       = (v0 - mu) * rs * gamma[tid]       + beta[tid];
    orow[tid + 256] = (v1 - mu) * rs * gamma[tid + 256] + beta[tid + 256];
    orow[tid + 512] = (v2 - mu) * rs * gamma[tid + 512] + beta[tid + 512];
}

// ============================================================================
// Launch
// ============================================================================
extern "C" void kernel_launch(void* const* d_in, const int* in_sizes, int n_in,
                              void* d_out, int out_size)
{
    const float* Qin  = (const float*)d_in[0];
    const float* Kin  = (const float*)d_in[1];
    const float* Vin  = (const float*)d_in[2];
    const int*   mask = (const int*)d_in[3];        // bool -> int32 0/1
    const float* Wq = (const float*)d_in[4];
    const float* bq = (const float*)d_in[5];
    const float* Wk = (const float*)d_in[6];
    const float* bk = (const float*)d_in[7];
    const float* Wv = (const float*)d_in[8];
    const float* bv = (const float*)d_in[9];
    const float* Wo = (const float*)d_in[10];
    const float* bo = (const float*)d_in[11];
    const float* gamma = (const float*)d_in[12];
    const float* beta  = (const float*)d_in[13];
    float* out = (float*)d_out;

    float *gq, *gk, *gv, *gctx, *gtmp;
    uint32_t* gmb;
    cudaGetSymbolAddress((void**)&gq,   g_q);
    cudaGetSymbolAddress((void**)&gk,   g_k);
    cudaGetSymbolAddress((void**)&gv,   g_v);
    cudaGetSymbolAddress((void**)&gctx, g_ctx);
    cudaGetSymbolAddress((void**)&gtmp, g_tmp);
    cudaGetSymbolAddress((void**)&gmb,  g_mbits);

    // pack mask: total words = BB*SS*(SS/32) = 524288; 16 words/warp
    mask_pack_kernel<<<4096, 256>>>(mask, gmb);

    dim3 gemm_grid(DM / 128, M_TOT / 128);   // (6, 64)
    gemm_tc_kernel<false><<<gemm_grid, 256>>>(Qin, Wq, bq, nullptr, gq);
    gemm_tc_kernel<false><<<gemm_grid, 256>>>(Kin, Wk, bk, nullptr, gk);
    gemm_tc_kernel<false><<<gemm_grid, 256>>>(Vin, Wv, bv, nullptr, gv);

    attn_tc_kernel<<<dim3(SS / 128, NH, BB), 256>>>(gmb);

    gemm_tc_kernel<true><<<gemm_grid, 256>>>(gctx, Wo, bo, Qin, gtmp);

    ln_kernel<<<M_TOT, 256>>>(gtmp, gamma, beta, out);
}

// round 6
// speedup vs baseline: 10.3021x; 1.3113x over previous
#include <cuda_runtime.h>
#include <cuda_bf16.h>
#include <math.h>
#include <stdint.h>

#define BB     4
#define SS     2048
#define DM     768
#define NH     12
#define DKH    64
#define M_TOT  (BB*SS)   // 8192

// -------- scratch (static device arrays; no runtime allocation) --------
__device__ __nv_bfloat16 g_qb[M_TOT*DM];     // Q proj (bf16)
__device__ __nv_bfloat16 g_kb[M_TOT*DM];     // K proj
__device__ __nv_bfloat16 g_vb[M_TOT*DM];     // V proj
__device__ __nv_bfloat16 g_ah[M_TOT*DM];     // A hi (input splits / ctx hi)
__device__ __nv_bfloat16 g_al[M_TOT*DM];     // A lo (input splits / ctx lo)
__device__ __nv_bfloat16 g_wh[4*DM*DM];      // weight hi x4
__device__ __nv_bfloat16 g_wl[4*DM*DM];      // weight lo x4
__device__ float    g_tmp[M_TOT*DM];
__device__ uint32_t g_mbits[BB*SS*(SS/32)];  // packed mask bits

// ============================================================================
// helpers
// ============================================================================
__device__ __forceinline__ uint32_t smem_u32(const void* p) {
    return (uint32_t)__cvta_generic_to_shared(p);
}
__device__ __forceinline__ void ldsm4(uint32_t& r0, uint32_t& r1, uint32_t& r2, uint32_t& r3, uint32_t addr) {
    asm volatile("ldmatrix.sync.aligned.m8n8.x4.shared.b16 {%0,%1,%2,%3}, [%4];"
                 : "=r"(r0), "=r"(r1), "=r"(r2), "=r"(r3) : "r"(addr));
}
__device__ __forceinline__ void ldsm4t(uint32_t& r0, uint32_t& r1, uint32_t& r2, uint32_t& r3, uint32_t addr) {
    asm volatile("ldmatrix.sync.aligned.m8n8.x4.trans.shared.b16 {%0,%1,%2,%3}, [%4];"
                 : "=r"(r0), "=r"(r1), "=r"(r2), "=r"(r3) : "r"(addr));
}
__device__ __forceinline__ void mma_bf16(float* c, uint32_t a0, uint32_t a1, uint32_t a2, uint32_t a3,
                                         uint32_t b0, uint32_t b1) {
    asm volatile("mma.sync.aligned.m16n8k16.row.col.f32.bf16.bf16.f32 "
                 "{%0,%1,%2,%3},{%4,%5,%6,%7},{%8,%9},{%0,%1,%2,%3};"
                 : "+f"(c[0]), "+f"(c[1]), "+f"(c[2]), "+f"(c[3])
                 : "r"(a0), "r"(a1), "r"(a2), "r"(a3), "r"(b0), "r"(b1));
}
__device__ __forceinline__ uint32_t pack_bf16(float x, float y) {
    __nv_bfloat162 p;
    p.x = __float2bfloat16(x);
    p.y = __float2bfloat16(y);
    return *(uint32_t*)&p;
}
__device__ __forceinline__ void cpasync16(uint32_t dst, const void* src) {
    asm volatile("cp.async.cg.shared.global [%0], [%1], 16;" :: "r"(dst), "l"(src));
}
__device__ __forceinline__ void cp_commit() { asm volatile("cp.async.commit_group;"); }
template<int N> __device__ __forceinline__ void cp_wait() {
    asm volatile("cp.async.wait_group %0;" :: "n"(N));
}

// ============================================================================
// fp32 -> bf16 hi/lo split (vectorized, exact-grid)
// ============================================================================
__global__ __launch_bounds__(256) void split_kernel(const float* __restrict__ x,
                                                    __nv_bfloat16* __restrict__ hi,
                                                    __nv_bfloat16* __restrict__ lo)
{
    const size_t i = ((size_t)blockIdx.x * 256 + threadIdx.x) * 4;
    float4 v = *(const float4*)(x + i);
    float vv[4] = {v.x, v.y, v.z, v.w};
    __nv_bfloat16 h[4], l[4];
    #pragma unroll
    for (int j = 0; j < 4; j++) {
        h[j] = __float2bfloat16(vv[j]);
        l[j] = __float2bfloat16(vv[j] - __bfloat162float(h[j]));
    }
    *(uint2*)(hi + i) = *(uint2*)h;
    *(uint2*)(lo + i) = *(uint2*)l;
}

// ============================================================================
// Mask pack: int32 0/1 -> bit per key
// ============================================================================
__global__ __launch_bounds__(256) void mask_pack_kernel(const int* __restrict__ mask,
                                                        uint32_t* __restrict__ bits)
{
    const int warp = (blockIdx.x * blockDim.x + threadIdx.x) >> 5;
    const int lane = threadIdx.x & 31;
    const size_t base = (size_t)warp * 16 * 32;
    #pragma unroll
    for (int i = 0; i < 16; i++) {
        int v = mask[base + i * 32 + lane];
        unsigned bal = __ballot_sync(0xffffffffu, v != 0);
        if (lane == 0) bits[warp * 16 + i] = bal;
    }
}

// ============================================================================
// Tensor-core GEMM on pre-split bf16 operands, cp.async double-buffered.
// C[M,768] = (Ah+Al)(Wh+Wl) ~ Ah*Wh + Ah*Wl + Al*Wh, + bias (+ residual)
// 128x128 tile, BK=16, 48 k-steps, 8 warps (2m x 4n), warp tile 64x32.
// ============================================================================
#define AST 24    // A smem row stride (bf16) - bank-disjoint ldsm
#define BST 136   // B smem row stride (bf16) - bank-disjoint ldsm.trans
#define NKT 48

template<bool RESID, bool OUTBF16>
__global__ __launch_bounds__(256, 2) void gemm_tc_kernel(
    const __nv_bfloat16* __restrict__ Agh, const __nv_bfloat16* __restrict__ Agl,
    const __nv_bfloat16* __restrict__ Wgh, const __nv_bfloat16* __restrict__ Wgl,
    const float* __restrict__ bias, const float* __restrict__ resid,
    void* __restrict__ Cout)
{
    __shared__ __nv_bfloat16 Ah[2][128*AST];
    __shared__ __nv_bfloat16 Al[2][128*AST];
    __shared__ __nv_bfloat16 Bh[2][16*BST];
    __shared__ __nv_bfloat16 Bl[2][16*BST];

    const int tid  = threadIdx.x;
    const int wid  = tid >> 5;
    const int lane = tid & 31;
    const int m0   = blockIdx.y * 128;
    const int n0   = blockIdx.x * 128;
    const int warp_m = (wid & 1) * 64;
    const int warp_n = (wid >> 1) * 32;

    // staging maps (one 16B cp.async per array per thread)
    const int sar = tid >> 1;            // A row 0..127
    const int sac = (tid & 1) * 8;       // A col 0 or 8
    const int sbr = tid >> 4;            // B k row 0..15
    const int sbc = (tid & 15) * 8;      // B n col 0..120

    const uint32_t ah0 = smem_u32(Ah);
    const uint32_t al0 = smem_u32(Al);
    const uint32_t bh0 = smem_u32(Bh);
    const uint32_t bl0 = smem_u32(Bl);
    const uint32_t a_off = (uint32_t)(sar * AST + sac) * 2;
    const uint32_t b_off = (uint32_t)(sbr * BST + sbc) * 2;

    const __nv_bfloat16* a_srch = Agh + (size_t)(m0 + sar) * DM + sac;
    const __nv_bfloat16* a_srcl = Agl + (size_t)(m0 + sar) * DM + sac;
    const __nv_bfloat16* b_srch = Wgh + (size_t)sbr * DM + n0 + sbc;
    const __nv_bfloat16* b_srcl = Wgl + (size_t)sbr * DM + n0 + sbc;

    // ldmatrix lane addressing
    const int lrow = lane & 7;
    const int lsel = lane >> 3;
    const int arow_f = lrow + ((lsel & 1) ? 8 : 0);
    const int akb    = (lsel & 2) ? 16 : 0;
    const int bkr    = lrow + ((lsel & 1) ? 8 : 0);
    const int bn_sub = (lsel & 2) ? 8 : 0;

    float acc[4][4][4] = {};

    // prefetch stage 0
    {
        cpasync16(ah0 + a_off, a_srch);
        cpasync16(al0 + a_off, a_srcl);
        cpasync16(bh0 + b_off, b_srch);
        cpasync16(bl0 + b_off, b_srcl);
        cp_commit();
    }

    for (int kt = 0; kt < NKT; kt++) {
        if (kt + 1 < NKT) {
            const int s  = (kt + 1) & 1;
            const int k0 = (kt + 1) * 16;
            cpasync16(ah0 + (uint32_t)(s * 128 * AST * 2) + a_off, a_srch + k0);
            cpasync16(al0 + (uint32_t)(s * 128 * AST * 2) + a_off, a_srcl + k0);
            cpasync16(bh0 + (uint32_t)(s * 16 * BST * 2) + b_off, b_srch + (size_t)k0 * DM);
            cpasync16(bl0 + (uint32_t)(s * 16 * BST * 2) + b_off, b_srcl + (size_t)k0 * DM);
            cp_commit();
            cp_wait<1>();
        } else {
            cp_wait<0>();
        }
        __syncthreads();

        const int s = kt & 1;
        const uint32_t ah_s = ah0 + (uint32_t)(s * 128 * AST * 2);
        const uint32_t al_s = al0 + (uint32_t)(s * 128 * AST * 2);
        const uint32_t bh_s = bh0 + (uint32_t)(s * 16 * BST * 2);
        const uint32_t bl_s = bl0 + (uint32_t)(s * 16 * BST * 2);

        uint32_t ahf[4][4], alf[4][4];
        #pragma unroll
        for (int t = 0; t < 4; t++) {
            uint32_t off = (uint32_t)((warp_m + t*16 + arow_f) * AST * 2 + akb);
            ldsm4(ahf[t][0], ahf[t][1], ahf[t][2], ahf[t][3], ah_s + off);
            ldsm4(alf[t][0], alf[t][1], alf[t][2], alf[t][3], al_s + off);
        }
        #pragma unroll
        for (int u = 0; u < 2; u++) {
            uint32_t off = (uint32_t)(bkr * BST * 2 + (warp_n + u*16 + bn_sub) * 2);
            uint32_t h0, h1, h2, h3, l0, l1, l2, l3;
            ldsm4t(h0, h1, h2, h3, bh_s + off);
            ldsm4t(l0, l1, l2, l3, bl_s + off);
            #pragma unroll
            for (int t = 0; t < 4; t++) {
                mma_bf16(acc[t][2*u],   ahf[t][0], ahf[t][1], ahf[t][2], ahf[t][3], h0, h1);
                mma_bf16(acc[t][2*u],   ahf[t][0], ahf[t][1], ahf[t][2], ahf[t][3], l0, l1);
                mma_bf16(acc[t][2*u],   alf[t][0], alf[t][1], alf[t][2], alf[t][3], h0, h1);
                mma_bf16(acc[t][2*u+1], ahf[t][0], ahf[t][1], ahf[t][2], ahf[t][3], h2, h3);
                mma_bf16(acc[t][2*u+1], ahf[t][0], ahf[t][1], ahf[t][2], ahf[t][3], l2, l3);
                mma_bf16(acc[t][2*u+1], alf[t][0], alf[t][1], alf[t][2], alf[t][3], h2, h3);
            }
        }
        __syncthreads();
    }

    // epilogue
    const int g  = lane >> 2;
    const int t4 = lane & 3;
    #pragma unroll
    for (int t = 0; t < 4; t++) {
        #pragma unroll
        for (int n = 0; n < 4; n++) {
            int row0 = m0 + warp_m + t*16 + g;
            int row1 = row0 + 8;
            int col  = n0 + warp_n + n*8 + t4*2;
            float2 bi = *(const float2*)(bias + col);
            float2 o0, o1;
            o0.x = acc[t][n][0] + bi.x;  o0.y = acc[t][n][1] + bi.y;
            o1.x = acc[t][n][2] + bi.x;  o1.y = acc[t][n][3] + bi.y;
            if (RESID) {
                float2 r0 = *(const float2*)(resid + (size_t)row0 * DM + col);
                float2 r1 = *(const float2*)(resid + (size_t)row1 * DM + col);
                o0.x += r0.x; o0.y += r0.y;
                o1.x += r1.x; o1.y += r1.y;
            }
            if (OUTBF16) {
                __nv_bfloat16* C = (__nv_bfloat16*)Cout;
                uint32_t p0 = pack_bf16(o0.x, o0.y);
                uint32_t p1 = pack_bf16(o1.x, o1.y);
                *(uint32_t*)(C + (size_t)row0 * DM + col) = p0;
                *(uint32_t*)(C + (size_t)row1 * DM + col) = p1;
            } else {
                float* C = (float*)Cout;
                *(float2*)(C + (size_t)row0 * DM + col) = o0;
                *(float2*)(C + (size_t)row1 * DM + col) = o1;
            }
        }
    }
}

// ============================================================================
// Tensor-core flash attention (bf16 in, hi/lo bf16 ctx out).
// CTA: 128 q rows x one (b,h). 8 warps x 16 q rows. 64-key tiles.
// ============================================================================
#define KST 72

__global__ __launch_bounds__(256, 2) void attn_tc_kernel(const uint32_t* __restrict__ mbits)
{
    __shared__ __nv_bfloat16 s_buf[2 * 64 * KST];   // Q stage overlays K+V
    __nv_bfloat16* Ks = s_buf;
    __nv_bfloat16* Vs = s_buf + 64 * KST;

    const int tid  = threadIdx.x;
    const int wid  = tid >> 5;
    const int lane = tid & 31;
    const int b    = blockIdx.z;
    const int h    = blockIdx.y;
    const int q0   = blockIdx.x * 128;
    const int g    = lane >> 2;
    const int t4   = lane & 3;

    // ---- stage Q tile [128 x 64] bf16 ----
    {
        const int r  = tid >> 1;
        const int hh = (tid & 1) * 32;
        const uint4* src = (const uint4*)(g_qb + (size_t)(b * SS + q0 + r) * DM + h * DKH + hh);
        uint4* dst = (uint4*)(s_buf + r * KST + hh);
        dst[0] = src[0]; dst[1] = src[1]; dst[2] = src[2]; dst[3] = src[3];
    }
    __syncthreads();

    // ---- Q fragments ----
    uint32_t qa[4][4];
    {
        const uint32_t base = smem_u32(s_buf);
        const int row  = wid * 16 + (lane & 15);
        const int colh = (lane >> 4) * 8;
        #pragma unroll
        for (int j = 0; j < 4; j++)
            ldsm4(qa[j][0], qa[j][1], qa[j][2], qa[j][3],
                  base + (uint32_t)((row * KST + j * 16 + colh) * 2));
    }

    float o[8][4] = {};
    float ls0 = 0.f, ls1 = 0.f;

    const __nv_bfloat16* kg = g_kb + (size_t)(b * SS) * DM + h * DKH;
    const __nv_bfloat16* vg = g_vb + (size_t)(b * SS) * DM + h * DKH;
    const uint32_t* mrow0 = mbits + ((size_t)(b * SS + q0 + wid * 16 + g)) * (SS/32);
    const uint32_t* mrow1 = mrow0 + 8 * (SS/32);

    const uint32_t ks_base = smem_u32(Ks);
    const uint32_t vs_base = smem_u32(Vs);

    const int krow = (lane & 7) + ((lane >> 4) ? 8 : 0);
    const int kcol = ((lane >> 3) & 1) * 8;
    const int vrow = (lane & 7) + (((lane >> 3) & 1) ? 8 : 0);
    const int vcol = (lane >> 4) * 8;
    const uint32_t kaddr0 = ks_base + (uint32_t)((krow * KST + kcol) * 2);
    const uint32_t vaddr0 = vs_base + (uint32_t)((vrow * KST + vcol) * 2);

    const int srow = tid >> 2;         // staging row 0..63
    const int scol = (tid & 3) * 16;   // staging col base (16 bf16 = 32B)

    for (int k0 = 0; k0 < SS; k0 += 64) {
        __syncthreads();
        {
            const uint4* kp = (const uint4*)(kg + (size_t)(k0 + srow) * DM + scol);
            const uint4* vp = (const uint4*)(vg + (size_t)(k0 + srow) * DM + scol);
            uint4* kd = (uint4*)(Ks + srow * KST + scol);
            uint4* vd = (uint4*)(Vs + srow * KST + scol);
            kd[0] = kp[0]; kd[1] = kp[1];
            vd[0] = vp[0]; vd[1] = vp[1];
        }
        __syncthreads();

        // ---- S = Q K^T ----
        float c[8][4] = {};
        #pragma unroll
        for (int np = 0; np < 4; np++) {
            #pragma unroll
            for (int j = 0; j < 4; j++) {
                uint32_t r0, r1, r2, r3;
                ldsm4(r0, r1, r2, r3, kaddr0 + (uint32_t)((np*16*KST + j*16) * 2));
                mma_bf16(c[2*np],   qa[j][0], qa[j][1], qa[j][2], qa[j][3], r0, r1);
                mma_bf16(c[2*np+1], qa[j][0], qa[j][1], qa[j][2], qa[j][3], r2, r3);
            }
        }

        // ---- mask + exp + row-sum ----
        const int kw = k0 >> 5;
        const uint32_t m0a = mrow0[kw], m0b = mrow0[kw+1];
        const uint32_t m1a = mrow1[kw], m1b = mrow1[kw+1];
        #pragma unroll
        for (int nt = 0; nt < 8; nt++) {
            const int colb = nt * 8 + 2 * t4;
            const uint32_t w0 = (colb & 32) ? m0b : m0a;
            const uint32_t w1 = (colb & 32) ? m1b : m1a;
            const int bit = colb & 31;
            float p0 = ((w0 >> bit)     & 1u) ? 0.f : __expf(c[nt][0] * 0.125f);
            float p1 = ((w0 >> (bit+1)) & 1u) ? 0.f : __expf(c[nt][1] * 0.125f);
            float p2 = ((w1 >> bit)     & 1u) ? 0.f : __expf(c[nt][2] * 0.125f);
            float p3 = ((w1 >> (bit+1)) & 1u) ? 0.f : __expf(c[nt][3] * 0.125f);
            ls0 += p0 + p1;
            ls1 += p2 + p3;
            c[nt][0] = p0; c[nt][1] = p1; c[nt][2] = p2; c[nt][3] = p3;
        }

        // ---- repack P ----
        uint32_t pa[4][4];
        #pragma unroll
        for (int j = 0; j < 4; j++) {
            pa[j][0] = pack_bf16(c[2*j][0],   c[2*j][1]);
            pa[j][1] = pack_bf16(c[2*j][2],   c[2*j][3]);
            pa[j][2] = pack_bf16(c[2*j+1][0], c[2*j+1][1]);
            pa[j][3] = pack_bf16(c[2*j+1][2], c[2*j+1][3]);
        }

        // ---- O += P V ----
        #pragma unroll
        for (int np = 0; np < 4; np++) {
            #pragma unroll
            for (int j = 0; j < 4; j++) {
                uint32_t r0, r1, r2, r3;
                ldsm4t(r0, r1, r2, r3, vaddr0 + (uint32_t)((j*16*KST + np*16) * 2));
                mma_bf16(o[2*np],   pa[j][0], pa[j][1], pa[j][2], pa[j][3], r0, r1);
                mma_bf16(o[2*np+1], pa[j][0], pa[j][1], pa[j][2], pa[j][3], r2, r3);
            }
        }
    }

    // ---- reduce, normalize, write ctx as hi/lo bf16 split ----
    ls0 += __shfl_xor_sync(0xffffffffu, ls0, 1);
    ls0 += __shfl_xor_sync(0xffffffffu, ls0, 2);
    ls1 += __shfl_xor_sync(0xffffffffu, ls1, 1);
    ls1 += __shfl_xor_sync(0xffffffffu, ls1, 2);
    const float inv0 = 1.f / ls0;
    const float inv1 = 1.f / ls1;

    const size_t r0off = (size_t)(b * SS + q0 + wid * 16 + g) * DM + h * DKH;
    const size_t r1off = r0off + 8 * DM;
    #pragma unroll
    for (int nt = 0; nt < 8; nt++) {
        const int col = nt * 8 + 2 * t4;
        float x0 = o[nt][0] * inv0, x1 = o[nt][1] * inv0;
        float y0 = o[nt][2] * inv1, y1 = o[nt][3] * inv1;
        __nv_bfloat16 hx0 = __float2bfloat16(x0);
        __nv_bfloat16 hx1 = __float2bfloat16(x1);
        __nv_bfloat16 hy0 = __float2bfloat16(y0);
        __nv_bfloat16 hy1 = __float2bfloat16(y1);
        uint32_t ph0 = pack_bf16(__bfloat162float(hx0), __bfloat162float(hx1));
        uint32_t ph1 = pack_bf16(__bfloat162float(hy0), __bfloat162float(hy1));
        uint32_t pl0 = pack_bf16(x0 - __bfloat162float(hx0), x1 - __bfloat162float(hx1));
        uint32_t pl1 = pack_bf16(y0 - __bfloat162float(hy0), y1 - __bfloat162float(hy1));
        *(uint32_t*)(g_ah + r0off + col) = ph0;
        *(uint32_t*)(g_al + r0off + col) = pl0;
        *(uint32_t*)(g_ah + r1off + col) = ph1;
        *(uint32_t*)(g_al + r1off + col) = pl1;
    }
}

// ============================================================================
// LayerNorm: 1 block per row, 256 threads, 3 elements each
// ============================================================================
__global__ __launch_bounds__(256) void ln_kernel(
    const float* __restrict__ x,
    const float* __restrict__ gamma, const float* __restrict__ beta,
    float* __restrict__ out)
{
    const int row = blockIdx.x;
    const int tid = threadIdx.x;
    const float* xr = x + (size_t)row * DM;

    float v0 = xr[tid];
    float v1 = xr[tid + 256];
    float v2 = xr[tid + 512];
    float s  = v0 + v1 + v2;
    float sq = v0 * v0 + v1 * v1 + v2 * v2;

    #pragma unroll
    for (int o = 16; o > 0; o >>= 1) {
        s  += __shfl_xor_sync(0xffffffffu, s,  o);
        sq += __shfl_xor_sync(0xffffffffu, sq, o);
    }
    __shared__ float reds[8], redq[8];
    const int wid = tid >> 5, lid = tid & 31;
    if (lid == 0) { reds[wid] = s; redq[wid] = sq; }
    __syncthreads();
    float ts = 0.f, tq = 0.f;
    #pragma unroll
    for (int i = 0; i < 8; i++) { ts += reds[i]; tq += redq[i]; }

    const float mu  = ts * (1.f / DM);
    const float var = tq * (1.f / DM) - mu * mu;
    const float rs  = rsqrtf(var + 1e-5f);

    float* orow = out + (size_t)row * DM;
    orow[tid]       = (v0 - mu) * rs * gamma[tid]       + beta[tid];
    orow[tid + 256] = (v1 - mu) * rs * gamma[tid + 256] + beta[tid + 256];
    orow[tid + 512] = (v2 - mu) * rs * gamma[tid + 512] + beta[tid + 512];
}

// ============================================================================
// Launch
// ============================================================================
extern "C" void kernel_launch(void* const* d_in, const int* in_sizes, int n_in,
                              void* d_out, int out_size)
{
    const float* Qin  = (const float*)d_in[0];
    const float* Kin  = (const float*)d_in[1];
    const float* Vin  = (const float*)d_in[2];
    const int*   mask = (const int*)d_in[3];
    const float* Wq = (const float*)d_in[4];
    const float* bq = (const float*)d_in[5];
    const float* Wk = (const float*)d_in[6];
    const float* bk = (const float*)d_in[7];
    const float* Wv = (const float*)d_in[8];
    const float* bv = (const float*)d_in[9];
    const float* Wo = (const float*)d_in[10];
    const float* bo = (const float*)d_in[11];
    const float* gamma = (const float*)d_in[12];
    const float* beta  = (const float*)d_in[13];
    float* out = (float*)d_out;

    __nv_bfloat16 *gqb, *gkb, *gvb, *gah, *gal, *gwh, *gwl;
    float* gtmp;
    uint32_t* gmb;
    cudaGetSymbolAddress((void**)&gqb, g_qb);
    cudaGetSymbolAddress((void**)&gkb, g_kb);
    cudaGetSymbolAddress((void**)&gvb, g_vb);
    cudaGetSymbolAddress((void**)&gah, g_ah);
    cudaGetSymbolAddress((void**)&gal, g_al);
    cudaGetSymbolAddress((void**)&gwh, g_wh);
    cudaGetSymbolAddress((void**)&gwl, g_wl);
    cudaGetSymbolAddress((void**)&gtmp, g_tmp);
    cudaGetSymbolAddress((void**)&gmb,  g_mbits);

    mask_pack_kernel<<<4096, 256>>>(mask, gmb);

    // weight splits (768*768/4/256 = 576 blocks each)
    split_kernel<<<576, 256>>>(Wq, gwh + 0*DM*DM, gwl + 0*DM*DM);
    split_kernel<<<576, 256>>>(Wk, gwh + 1*DM*DM, gwl + 1*DM*DM);
    split_kernel<<<576, 256>>>(Wv, gwh + 2*DM*DM, gwl + 2*DM*DM);
    split_kernel<<<576, 256>>>(Wo, gwh + 3*DM*DM, gwl + 3*DM*DM);

    dim3 gemm_grid(DM / 128, M_TOT / 128);   // (6, 64)

    // Q projection
    split_kernel<<<6144, 256>>>(Qin, gah, gal);
    gemm_tc_kernel<false, true><<<gemm_grid, 256>>>(gah, gal, gwh + 0*DM*DM, gwl + 0*DM*DM, bq, nullptr, gqb);
    // K projection
    split_kernel<<<6144, 256>>>(Kin, gah, gal);
    gemm_tc_kernel<false, true><<<gemm_grid, 256>>>(gah, gal, gwh + 1*DM*DM, gwl + 1*DM*DM, bk, nullptr, gkb);
    // V projection
    split_kernel<<<6144, 256>>>(Vin, gah, gal);
    gemm_tc_kernel<false, true><<<gemm_grid, 256>>>(gah, gal, gwh + 2*DM*DM, gwl + 2*DM*DM, bv, nullptr, gvb);

    // attention (writes ctx hi/lo into gah/gal)
    attn_tc_kernel<<<dim3(SS / 128, NH, BB), 256>>>(gmb);

    // output projection + residual
    gemm_tc_kernel<true, false><<<gemm_grid, 256>>>(gah, gal, gwh + 3*DM*DM, gwl + 3*DM*DM, bo, Qin, gtmp);

    ln_kernel<<<M_TOT, 256>>>(gtmp, gamma, beta, out);
}

// round 7
// speedup vs baseline: 11.0550x; 1.0731x over previous
#include <cuda_runtime.h>
#include <cuda_bf16.h>
#include <math.h>
#include <stdint.h>

#define BB     4
#define SS     2048
#define DM     768
#define NH     12
#define DKH    64
#define M_TOT  (BB*SS)   // 8192

// -------- scratch (static device arrays; no runtime allocation) --------
__device__ __nv_bfloat16 g_qkvb[3*M_TOT*DM];   // Q,K,V projections (bf16)
__device__ __nv_bfloat16 g_ah[3*M_TOT*DM];     // input splits hi / ctx hi
__device__ __nv_bfloat16 g_al[3*M_TOT*DM];     // input splits lo / ctx lo
__device__ __nv_bfloat16 g_wh[4*DM*DM];        // weight hi x4
__device__ __nv_bfloat16 g_wl[4*DM*DM];        // weight lo x4
__device__ float    g_tmp[M_TOT*DM];
__device__ uint32_t g_mbits[BB*SS*(SS/32)];    // packed mask bits

// ============================================================================
// helpers
// ============================================================================
__device__ __forceinline__ uint32_t smem_u32(const void* p) {
    return (uint32_t)__cvta_generic_to_shared(p);
}
__device__ __forceinline__ void ldsm4(uint32_t& r0, uint32_t& r1, uint32_t& r2, uint32_t& r3, uint32_t addr) {
    asm volatile("ldmatrix.sync.aligned.m8n8.x4.shared.b16 {%0,%1,%2,%3}, [%4];"
                 : "=r"(r0), "=r"(r1), "=r"(r2), "=r"(r3) : "r"(addr));
}
__device__ __forceinline__ void ldsm4t(uint32_t& r0, uint32_t& r1, uint32_t& r2, uint32_t& r3, uint32_t addr) {
    asm volatile("ldmatrix.sync.aligned.m8n8.x4.trans.shared.b16 {%0,%1,%2,%3}, [%4];"
                 : "=r"(r0), "=r"(r1), "=r"(r2), "=r"(r3) : "r"(addr));
}
__device__ __forceinline__ void mma_bf16(float* c, uint32_t a0, uint32_t a1, uint32_t a2, uint32_t a3,
                                         uint32_t b0, uint32_t b1) {
    asm volatile("mma.sync.aligned.m16n8k16.row.col.f32.bf16.bf16.f32 "
                 "{%0,%1,%2,%3},{%4,%5,%6,%7},{%8,%9},{%0,%1,%2,%3};"
                 : "+f"(c[0]), "+f"(c[1]), "+f"(c[2]), "+f"(c[3])
                 : "r"(a0), "r"(a1), "r"(a2), "r"(a3), "r"(b0), "r"(b1));
}
__device__ __forceinline__ uint32_t pack_bf16(float x, float y) {
    __nv_bfloat162 p;
    p.x = __float2bfloat16(x);
    p.y = __float2bfloat16(y);
    return *(uint32_t*)&p;
}
__device__ __forceinline__ void cpasync16(uint32_t dst, const void* src) {
    asm volatile("cp.async.cg.shared.global [%0], [%1], 16;" :: "r"(dst), "l"(src));
}
__device__ __forceinline__ void cp_commit() { asm volatile("cp.async.commit_group;"); }
template<int N> __device__ __forceinline__ void cp_wait() {
    asm volatile("cp.async.wait_group %0;" :: "n"(N));
}

// ============================================================================
// fp32 -> bf16 hi/lo split; batched over blockIdx.y (up to 4 sources)
// ============================================================================
__global__ __launch_bounds__(256) void split4_kernel(
    const float* __restrict__ x0, const float* __restrict__ x1,
    const float* __restrict__ x2, const float* __restrict__ x3,
    __nv_bfloat16* __restrict__ hi, __nv_bfloat16* __restrict__ lo,
    size_t stride)
{
    const int z = blockIdx.y;
    const float* x = (z == 0) ? x0 : (z == 1) ? x1 : (z == 2) ? x2 : x3;
    const size_t i = ((size_t)blockIdx.x * 256 + threadIdx.x) * 4;
    const size_t o = (size_t)z * stride + i;
    float4 v = *(const float4*)(x + i);
    float vv[4] = {v.x, v.y, v.z, v.w};
    __nv_bfloat16 h[4], l[4];
    #pragma unroll
    for (int j = 0; j < 4; j++) {
        h[j] = __float2bfloat16(vv[j]);
        l[j] = __float2bfloat16(vv[j] - __bfloat162float(h[j]));
    }
    *(uint2*)(hi + o) = *(uint2*)h;
    *(uint2*)(lo + o) = *(uint2*)l;
}

// ============================================================================
// Mask pack: int32 0/1 -> bit per key
// ============================================================================
__global__ __launch_bounds__(256) void mask_pack_kernel(const int* __restrict__ mask,
                                                        uint32_t* __restrict__ bits)
{
    const int warp = (blockIdx.x * blockDim.x + threadIdx.x) >> 5;
    const int lane = threadIdx.x & 31;
    const size_t base = (size_t)warp * 16 * 32;
    #pragma unroll
    for (int i = 0; i < 16; i++) {
        int v = mask[base + i * 32 + lane];
        unsigned bal = __ballot_sync(0xffffffffu, v != 0);
        if (lane == 0) bits[warp * 16 + i] = bal;
    }
}

// ============================================================================
// Tensor-core GEMM on pre-split bf16 operands, cp.async double-buffered.
// MULTI: blockIdx.z in {0,1,2} selects A/W/bias/out slice (QKV merged).
// ============================================================================
#define AST 24    // A smem row stride (bf16)
#define BST 136   // B smem row stride (bf16)
#define NKT 48

template<bool MULTI, bool RESID, bool OUTBF16>
__global__ __launch_bounds__(256, 2) void gemm_tc_kernel(
    const __nv_bfloat16* __restrict__ Agh, const __nv_bfloat16* __restrict__ Agl,
    const __nv_bfloat16* __restrict__ Wgh, const __nv_bfloat16* __restrict__ Wgl,
    const float* __restrict__ b0, const float* __restrict__ b1,
    const float* __restrict__ b2,
    const float* __restrict__ resid, void* __restrict__ Cout)
{
    __shared__ __nv_bfloat16 Ah[2][128*AST];
    __shared__ __nv_bfloat16 Al[2][128*AST];
    __shared__ __nv_bfloat16 Bh[2][16*BST];
    __shared__ __nv_bfloat16 Bl[2][16*BST];

    const int z = MULTI ? blockIdx.z : 0;
    const float* bias = MULTI ? ((z == 0) ? b0 : (z == 1) ? b1 : b2) : b0;
    const size_t a_base = (size_t)z * M_TOT * DM;
    const size_t w_base = (size_t)z * DM * DM;

    const int tid  = threadIdx.x;
    const int wid  = tid >> 5;
    const int lane = tid & 31;
    const int m0   = blockIdx.y * 128;
    const int n0   = blockIdx.x * 128;
    const int warp_m = (wid & 1) * 64;
    const int warp_n = (wid >> 1) * 32;

    const int sar = tid >> 1;
    const int sac = (tid & 1) * 8;
    const int sbr = tid >> 4;
    const int sbc = (tid & 15) * 8;

    const uint32_t ah0 = smem_u32(Ah);
    const uint32_t al0 = smem_u32(Al);
    const uint32_t bh0 = smem_u32(Bh);
    const uint32_t bl0 = smem_u32(Bl);
    const uint32_t a_off = (uint32_t)(sar * AST + sac) * 2;
    const uint32_t b_off = (uint32_t)(sbr * BST + sbc) * 2;

    const __nv_bfloat16* a_srch = Agh + a_base + (size_t)(m0 + sar) * DM + sac;
    const __nv_bfloat16* a_srcl = Agl + a_base + (size_t)(m0 + sar) * DM + sac;
    const __nv_bfloat16* b_srch = Wgh + w_base + (size_t)sbr * DM + n0 + sbc;
    const __nv_bfloat16* b_srcl = Wgl + w_base + (size_t)sbr * DM + n0 + sbc;

    const int lrow = lane & 7;
    const int lsel = lane >> 3;
    const int arow_f = lrow + ((lsel & 1) ? 8 : 0);
    const int akb    = (lsel & 2) ? 16 : 0;
    const int bkr    = lrow + ((lsel & 1) ? 8 : 0);
    const int bn_sub = (lsel & 2) ? 8 : 0;

    float acc[4][4][4] = {};

    {
        cpasync16(ah0 + a_off, a_srch);
        cpasync16(al0 + a_off, a_srcl);
        cpasync16(bh0 + b_off, b_srch);
        cpasync16(bl0 + b_off, b_srcl);
        cp_commit();
    }

    for (int kt = 0; kt < NKT; kt++) {
        if (kt + 1 < NKT) {
            const int s  = (kt + 1) & 1;
            const int k0 = (kt + 1) * 16;
            cpasync16(ah0 + (uint32_t)(s * 128 * AST * 2) + a_off, a_srch + k0);
            cpasync16(al0 + (uint32_t)(s * 128 * AST * 2) + a_off, a_srcl + k0);
            cpasync16(bh0 + (uint32_t)(s * 16 * BST * 2) + b_off, b_srch + (size_t)k0 * DM);
            cpasync16(bl0 + (uint32_t)(s * 16 * BST * 2) + b_off, b_srcl + (size_t)k0 * DM);
            cp_commit();
            cp_wait<1>();
        } else {
            cp_wait<0>();
        }
        __syncthreads();

        const int s = kt & 1;
        const uint32_t ah_s = ah0 + (uint32_t)(s * 128 * AST * 2);
        const uint32_t al_s = al0 + (uint32_t)(s * 128 * AST * 2);
        const uint32_t bh_s = bh0 + (uint32_t)(s * 16 * BST * 2);
        const uint32_t bl_s = bl0 + (uint32_t)(s * 16 * BST * 2);

        uint32_t ahf[4][4], alf[4][4];
        #pragma unroll
        for (int t = 0; t < 4; t++) {
            uint32_t off = (uint32_t)((warp_m + t*16 + arow_f) * AST * 2 + akb);
            ldsm4(ahf[t][0], ahf[t][1], ahf[t][2], ahf[t][3], ah_s + off);
            ldsm4(alf[t][0], alf[t][1], alf[t][2], alf[t][3], al_s + off);
        }
        #pragma unroll
        for (int u = 0; u < 2; u++) {
            uint32_t off = (uint32_t)(bkr * BST * 2 + (warp_n + u*16 + bn_sub) * 2);
            uint32_t h0, h1, h2, h3, l0, l1, l2, l3;
            ldsm4t(h0, h1, h2, h3, bh_s + off);
            ldsm4t(l0, l1, l2, l3, bl_s + off);
            #pragma unroll
            for (int t = 0; t < 4; t++) {
                mma_bf16(acc[t][2*u],   ahf[t][0], ahf[t][1], ahf[t][2], ahf[t][3], h0, h1);
                mma_bf16(acc[t][2*u],   ahf[t][0], ahf[t][1], ahf[t][2], ahf[t][3], l0, l1);
                mma_bf16(acc[t][2*u],   alf[t][0], alf[t][1], alf[t][2], alf[t][3], h0, h1);
                mma_bf16(acc[t][2*u+1], ahf[t][0], ahf[t][1], ahf[t][2], ahf[t][3], h2, h3);
                mma_bf16(acc[t][2*u+1], ahf[t][0], ahf[t][1], ahf[t][2], ahf[t][3], l2, l3);
                mma_bf16(acc[t][2*u+1], alf[t][0], alf[t][1], alf[t][2], alf[t][3], h2, h3);
            }
        }
        __syncthreads();
    }

    // epilogue
    const int g  = lane >> 2;
    const int t4 = lane & 3;
    #pragma unroll
    for (int t = 0; t < 4; t++) {
        #pragma unroll
        for (int n = 0; n < 4; n++) {
            int row0 = m0 + warp_m + t*16 + g;
            int row1 = row0 + 8;
            int col  = n0 + warp_n + n*8 + t4*2;
            float2 bi = *(const float2*)(bias + col);
            float2 o0, o1;
            o0.x = acc[t][n][0] + bi.x;  o0.y = acc[t][n][1] + bi.y;
            o1.x = acc[t][n][2] + bi.x;  o1.y = acc[t][n][3] + bi.y;
            if (RESID) {
                float2 r0 = *(const float2*)(resid + (size_t)row0 * DM + col);
                float2 r1 = *(const float2*)(resid + (size_t)row1 * DM + col);
                o0.x += r0.x; o0.y += r0.y;
                o1.x += r1.x; o1.y += r1.y;
            }
            if (OUTBF16) {
                __nv_bfloat16* C = (__nv_bfloat16*)Cout + (size_t)z * M_TOT * DM;
                *(uint32_t*)(C + (size_t)row0 * DM + col) = pack_bf16(o0.x, o0.y);
                *(uint32_t*)(C + (size_t)row1 * DM + col) = pack_bf16(o1.x, o1.y);
            } else {
                float* C = (float*)Cout;
                *(float2*)(C + (size_t)row0 * DM + col) = o0;
                *(float2*)(C + (size_t)row1 * DM + col) = o1;
            }
        }
    }
}

// ============================================================================
// Tensor-core flash attention, cp.async double-buffered K/V.
// CTA: 128 q rows x one (b,h). 8 warps x 16 q rows. 64-key tiles.
// smem: 2 stages x (K tile + V tile), 64x64 bf16 each, stride KST=72.
// Q staged once into stage0 area, consumed into registers before loop.
// ============================================================================
#define KST 72
#define KV_STAGE_ELEMS (2 * 64 * KST)    // K + V per stage (9216 elems)

__global__ __launch_bounds__(256, 2) void attn_tc_kernel(const uint32_t* __restrict__ mbits)
{
    __shared__ __nv_bfloat16 s_buf[2 * KV_STAGE_ELEMS];   // 36.9 KB

    const int tid  = threadIdx.x;
    const int wid  = tid >> 5;
    const int lane = tid & 31;
    const int b    = blockIdx.z;
    const int h    = blockIdx.y;
    const int q0   = blockIdx.x * 128;
    const int g    = lane >> 2;
    const int t4   = lane & 3;

    const __nv_bfloat16* qg = g_qkvb + 0 * (size_t)M_TOT * DM;
    const __nv_bfloat16* kg = g_qkvb + 1 * (size_t)M_TOT * DM + (size_t)(b * SS) * DM + h * DKH;
    const __nv_bfloat16* vg = g_qkvb + 2 * (size_t)M_TOT * DM + (size_t)(b * SS) * DM + h * DKH;

    // ---- stage Q tile [128 x 64] into s_buf (aliases stage 0) ----
    {
        const int r  = tid >> 1;
        const int hh = (tid & 1) * 32;
        const uint4* src = (const uint4*)(qg + (size_t)(b * SS + q0 + r) * DM + h * DKH + hh);
        uint4* dst = (uint4*)(s_buf + r * KST + hh);
        dst[0] = src[0]; dst[1] = src[1]; dst[2] = src[2]; dst[3] = src[3];
    }
    __syncthreads();

    // ---- Q fragments ----
    uint32_t qa[4][4];
    {
        const uint32_t base = smem_u32(s_buf);
        const int row  = wid * 16 + (lane & 15);
        const int colh = (lane >> 4) * 8;
        #pragma unroll
        for (int j = 0; j < 4; j++)
            ldsm4(qa[j][0], qa[j][1], qa[j][2], qa[j][3],
                  base + (uint32_t)((row * KST + j * 16 + colh) * 2));
    }
    __syncthreads();   // all warps done reading Q before stage-0 prefetch

    float o[8][4] = {};
    float ls0 = 0.f, ls1 = 0.f;

    const uint32_t* mrow0 = mbits + ((size_t)(b * SS + q0 + wid * 16 + g)) * (SS/32);
    const uint32_t* mrow1 = mrow0 + 8 * (SS/32);

    const uint32_t sb = smem_u32(s_buf);

    // ldmatrix per-lane offsets (within a K or V tile)
    const int krow = (lane & 7) + ((lane >> 4) ? 8 : 0);
    const int kcol = ((lane >> 3) & 1) * 8;
    const int vrow = (lane & 7) + (((lane >> 3) & 1) ? 8 : 0);
    const int vcol = (lane >> 4) * 8;
    const uint32_t k_lane_off = (uint32_t)((krow * KST + kcol) * 2);
    const uint32_t v_lane_off = (uint32_t)((vrow * KST + vcol) * 2);

    // staging map: K tile = 512 x 16B chunks, 2 per thread; same for V
    const int c0   = tid * 2;
    const int srow = c0 >> 3;            // 0..63
    const int scol = (c0 & 7) * 8;       // 0..56, two consecutive chunks
    const uint32_t st_off = (uint32_t)((srow * KST + scol) * 2);

    // prefetch tile 0 into stage 0
    {
        const __nv_bfloat16* kp = kg + (size_t)srow * DM + scol;
        const __nv_bfloat16* vp = vg + (size_t)srow * DM + scol;
        cpasync16(sb + st_off, kp);
        cpasync16(sb + st_off + 16, kp + 8);
        cpasync16(sb + (uint32_t)(64*KST*2) + st_off, vp);
        cpasync16(sb + (uint32_t)(64*KST*2) + st_off + 16, vp + 8);
        cp_commit();
    }

    for (int kt = 0; kt < SS/64; kt++) {
        if (kt + 1 < SS/64) {
            const uint32_t s_off = (uint32_t)(((kt + 1) & 1) * KV_STAGE_ELEMS * 2);
            const __nv_bfloat16* kp = kg + (size_t)((kt+1)*64 + srow) * DM + scol;
            const __nv_bfloat16* vp = vg + (size_t)((kt+1)*64 + srow) * DM + scol;
            cpasync16(sb + s_off + st_off, kp);
            cpasync16(sb + s_off + st_off + 16, kp + 8);
            cpasync16(sb + s_off + (uint32_t)(64*KST*2) + st_off, vp);
            cpasync16(sb + s_off + (uint32_t)(64*KST*2) + st_off + 16, vp + 8);
            cp_commit();
            cp_wait<1>();
        } else {
            cp_wait<0>();
        }
        __syncthreads();

        const uint32_t stage = (uint32_t)((kt & 1) * KV_STAGE_ELEMS * 2);
        const uint32_t kaddr0 = sb + stage + k_lane_off;
        const uint32_t vaddr0 = sb + stage + (uint32_t)(64*KST*2) + v_lane_off;

        // ---- S = Q K^T ----
        float c[8][4] = {};
        #pragma unroll
        for (int np = 0; np < 4; np++) {
            #pragma unroll
            for (int j = 0; j < 4; j++) {
                uint32_t r0, r1, r2, r3;
                ldsm4(r0, r1, r2, r3, kaddr0 + (uint32_t)((np*16*KST + j*16) * 2));
                mma_bf16(c[2*np],   qa[j][0], qa[j][1], qa[j][2], qa[j][3], r0, r1);
                mma_bf16(c[2*np+1], qa[j][0], qa[j][1], qa[j][2], qa[j][3], r2, r3);
            }
        }

        // ---- mask + exp + row-sum ----
        const int k0 = kt * 64;
        const int kw = k0 >> 5;
        const uint32_t m0a = mrow0[kw], m0b = mrow0[kw+1];
        const uint32_t m1a = mrow1[kw], m1b = mrow1[kw+1];
        const float SC = 0.125f * 1.44269504088896340736f;   // 1/sqrt(64) * log2(e)
        #pragma unroll
        for (int nt = 0; nt < 8; nt++) {
            const int colb = nt * 8 + 2 * t4;
            const uint32_t w0 = (colb & 32) ? m0b : m0a;
            const uint32_t w1 = (colb & 32) ? m1b : m1a;
            const int bit = colb & 31;
            float p0 = ((w0 >> bit)     & 1u) ? 0.f : exp2f(c[nt][0] * SC);
            float p1 = ((w0 >> (bit+1)) & 1u) ? 0.f : exp2f(c[nt][1] * SC);
            float p2 = ((w1 >> bit)     & 1u) ? 0.f : exp2f(c[nt][2] * SC);
            float p3 = ((w1 >> (bit+1)) & 1u) ? 0.f : exp2f(c[nt][3] * SC);
            ls0 += p0 + p1;
            ls1 += p2 + p3;
            c[nt][0] = p0; c[nt][1] = p1; c[nt][2] = p2; c[nt][3] = p3;
        }

        // ---- repack P ----
        uint32_t pa[4][4];
        #pragma unroll
        for (int j = 0; j < 4; j++) {
            pa[j][0] = pack_bf16(c[2*j][0],   c[2*j][1]);
            pa[j][1] = pack_bf16(c[2*j][2],   c[2*j][3]);
            pa[j][2] = pack_bf16(c[2*j+1][0], c[2*j+1][1]);
            pa[j][3] = pack_bf16(c[2*j+1][2], c[2*j+1][3]);
        }

        // ---- O += P V ----
        #pragma unroll
        for (int np = 0; np < 4; np++) {
            #pragma unroll
            for (int j = 0; j < 4; j++) {
                uint32_t r0, r1, r2, r3;
                ldsm4t(r0, r1, r2, r3, vaddr0 + (uint32_t)((j*16*KST + np*16) * 2));
                mma_bf16(o[2*np],   pa[j][0], pa[j][1], pa[j][2], pa[j][3], r0, r1);
                mma_bf16(o[2*np+1], pa[j][0], pa[j][1], pa[j][2], pa[j][3], r2, r3);
            }
        }
        __syncthreads();
    }

    // ---- reduce, normalize, write ctx as hi/lo bf16 split ----
    ls0 += __shfl_xor_sync(0xffffffffu, ls0, 1);
    ls0 += __shfl_xor_sync(0xffffffffu, ls0, 2);
    ls1 += __shfl_xor_sync(0xffffffffu, ls1, 1);
    ls1 += __shfl_xor_sync(0xffffffffu, ls1, 2);
    const float inv0 = 1.f / ls0;
    const float inv1 = 1.f / ls1;

    const size_t r0off = (size_t)(b * SS + q0 + wid * 16 + g) * DM + h * DKH;
    const size_t r1off = r0off + 8 * DM;
    #pragma unroll
    for (int nt = 0; nt < 8; nt++) {
        const int col = nt * 8 + 2 * t4;
        float x0 = o[nt][0] * inv0, x1 = o[nt][1] * inv0;
        float y0 = o[nt][2] * inv1, y1 = o[nt][3] * inv1;
        __nv_bfloat16 hx0 = __float2bfloat16(x0);
        __nv_bfloat16 hx1 = __float2bfloat16(x1);
        __nv_bfloat16 hy0 = __float2bfloat16(y0);
        __nv_bfloat16 hy1 = __float2bfloat16(y1);
        *(uint32_t*)(g_ah + r0off + col) = pack_bf16(__bfloat162float(hx0), __bfloat162float(hx1));
        *(uint32_t*)(g_al + r0off + col) = pack_bf16(x0 - __bfloat162float(hx0), x1 - __bfloat162float(hx1));
        *(uint32_t*)(g_ah + r1off + col) = pack_bf16(__bfloat162float(hy0), __bfloat162float(hy1));
        *(uint32_t*)(g_al + r1off + col) = pack_bf16(y0 - __bfloat162float(hy0), y1 - __bfloat162float(hy1));
    }
}

// ============================================================================
// LayerNorm: 1 block per row, 256 threads, 3 elements each
// ============================================================================
__global__ __launch_bounds__(256) void ln_kernel(
    const float* __restrict__ x,
    const float* __restrict__ gamma, const float* __restrict__ beta,
    float* __restrict__ out)
{
    const int row = blockIdx.x;
    const int tid = threadIdx.x;
    const float* xr = x + (size_t)row * DM;

    float v0 = xr[tid];
    float v1 = xr[tid + 256];
    float v2 = xr[tid + 512];
    float s  = v0 + v1 + v2;
    float sq = v0 * v0 + v1 * v1 + v2 * v2;

    #pragma unroll
    for (int o = 16; o > 0; o >>= 1) {
        s  += __shfl_xor_sync(0xffffffffu, s,  o);
        sq += __shfl_xor_sync(0xffffffffu, sq, o);
    }
    __shared__ float reds[8], redq[8];
    const int wid = tid >> 5, lid = tid & 31;
    if (lid == 0) { reds[wid] = s; redq[wid] = sq; }
    __syncthreads();
    float ts = 0.f, tq = 0.f;
    #pragma unroll
    for (int i = 0; i < 8; i++) { ts += reds[i]; tq += redq[i]; }

    const float mu  = ts * (1.f / DM);
    const float var = tq * (1.f / DM) - mu * mu;
    const float rs  = rsqrtf(var + 1e-5f);

    float* orow = out + (size_t)row * DM;
    orow[tid]       = (v0 - mu) * rs * gamma[tid]       + beta[tid];
    orow[tid + 256] = (v1 - mu) * rs * gamma[tid + 256] + beta[tid + 256];
    orow[tid + 512] = (v2 - mu) * rs * gamma[tid + 512] + beta[tid + 512];
}

// ============================================================================
// Launch
// ============================================================================
extern "C" void kernel_launch(void* const* d_in, const int* in_sizes, int n_in,
                              void* d_out, int out_size)
{
    const float* Qin  = (const float*)d_in[0];
    const float* Kin  = (const float*)d_in[1];
    const float* Vin  = (const float*)d_in[2];
    const int*   mask = (const int*)d_in[3];
    const float* Wq = (const float*)d_in[4];
    const float* bq = (const float*)d_in[5];
    const float* Wk = (const float*)d_in[6];
    const float* bk = (const float*)d_in[7];
    const float* Wv = (const float*)d_in[8];
    const float* bv = (const float*)d_in[9];
    const float* Wo = (const float*)d_in[10];
    const float* bo = (const float*)d_in[11];
    const float* gamma = (const float*)d_in[12];
    const float* beta  = (const float*)d_in[13];
    float* out = (float*)d_out;

    __nv_bfloat16 *gqkv, *gah, *gal, *gwh, *gwl;
    float* gtmp;
    uint32_t* gmb;
    cudaGetSymbolAddress((void**)&gqkv, g_qkvb);
    cudaGetSymbolAddress((void**)&gah,  g_ah);
    cudaGetSymbolAddress((void**)&gal,  g_al);
    cudaGetSymbolAddress((void**)&gwh,  g_wh);
    cudaGetSymbolAddress((void**)&gwl,  g_wl);
    cudaGetSymbolAddress((void**)&gtmp, g_tmp);
    cudaGetSymbolAddress((void**)&gmb,  g_mbits);

    mask_pack_kernel<<<4096, 256>>>(mask, gmb);

    // weight splits: 4 weights, 768*768/(256*4) = 576 blocks each
    split4_kernel<<<dim3(576, 4), 256>>>(Wq, Wk, Wv, Wo, gwh, gwl, (size_t)DM * DM);

    // input splits: Q,K,V -> gah/gal slices
    split4_kernel<<<dim3(6144, 3), 256>>>(Qin, Kin, Vin, Qin, gah, gal, (size_t)M_TOT * DM);

    // merged Q/K/V projection GEMM (1152 CTAs)
    gemm_tc_kernel<true, false, true><<<dim3(DM/128, M_TOT/128, 3), 256>>>(
        gah, gal, gwh, gwl, bq, bk, bv, nullptr, gqkv);

    // attention (writes ctx hi/lo into gah/gal slice 0)
    attn_tc_kernel<<<dim3(SS / 128, NH, BB), 256>>>(gmb);

    // output projection + residual
    gemm_tc_kernel<false, true, false><<<dim3(DM/128, M_TOT/128), 256>>>(
        gah, gal, gwh + 3*(size_t)DM*DM, gwl + 3*(size_t)DM*DM, bo, nullptr, nullptr, Qin, gtmp);

    ln_kernel<<<M_TOT, 256>>>(gtmp, gamma, beta, out);
}

// round 9
// speedup vs baseline: 15.5543x; 1.4070x over previous
#include <cuda_runtime.h>
#include <cuda_bf16.h>
#include <math.h>
#include <stdint.h>

#define BB     4
#define SS     2048
#define DM     768
#define NH     12
#define DKH    64
#define M_TOT  (BB*SS)   // 8192

// -------- scratch (static device arrays; no runtime allocation) --------
__device__ __nv_bfloat16 g_qkvb[3*M_TOT*DM];   // Q,K,V projections (bf16)
__device__ __nv_bfloat16 g_ab[3*M_TOT*DM];     // cast inputs / ctx (slice 0)
__device__ __nv_bfloat16 g_wb[4*DM*DM];        // cast weights x4
__device__ float    g_tmp[M_TOT*DM];
__device__ uint32_t g_mbits[BB*SS*(SS/32)];    // packed mask bits

// ============================================================================
// helpers
// ============================================================================
__device__ __forceinline__ uint32_t smem_u32(const void* p) {
    return (uint32_t)__cvta_generic_to_shared(p);
}
__device__ __forceinline__ void ldsm4(uint32_t& r0, uint32_t& r1, uint32_t& r2, uint32_t& r3, uint32_t addr) {
    asm volatile("ldmatrix.sync.aligned.m8n8.x4.shared.b16 {%0,%1,%2,%3}, [%4];"
                 : "=r"(r0), "=r"(r1), "=r"(r2), "=r"(r3) : "r"(addr));
}
__device__ __forceinline__ void ldsm4t(uint32_t& r0, uint32_t& r1, uint32_t& r2, uint32_t& r3, uint32_t addr) {
    asm volatile("ldmatrix.sync.aligned.m8n8.x4.trans.shared.b16 {%0,%1,%2,%3}, [%4];"
                 : "=r"(r0), "=r"(r1), "=r"(r2), "=r"(r3) : "r"(addr));
}
__device__ __forceinline__ void mma_bf16(float* c, uint32_t a0, uint32_t a1, uint32_t a2, uint32_t a3,
                                         uint32_t b0, uint32_t b1) {
    asm volatile("mma.sync.aligned.m16n8k16.row.col.f32.bf16.bf16.f32 "
                 "{%0,%1,%2,%3},{%4,%5,%6,%7},{%8,%9},{%0,%1,%2,%3};"
                 : "+f"(c[0]), "+f"(c[1]), "+f"(c[2]), "+f"(c[3])
                 : "r"(a0), "r"(a1), "r"(a2), "r"(a3), "r"(b0), "r"(b1));
}
__device__ __forceinline__ uint32_t pack_bf16(float x, float y) {
    __nv_bfloat162 p;
    p.x = __float2bfloat16(x);
    p.y = __float2bfloat16(y);
    return *(uint32_t*)&p;
}
__device__ __forceinline__ void cpasync16(uint32_t dst, const void* src) {
    asm volatile("cp.async.cg.shared.global [%0], [%1], 16;" :: "r"(dst), "l"(src));
}
__device__ __forceinline__ void cp_commit() { asm volatile("cp.async.commit_group;"); }
template<int N> __device__ __forceinline__ void cp_wait() {
    asm volatile("cp.async.wait_group %0;" :: "n"(N));
}

// ============================================================================
// fp32 -> bf16 cast; batched over blockIdx.y (up to 4 sources)
// ============================================================================
__global__ __launch_bounds__(256) void cast4_kernel(
    const float* __restrict__ x0, const float* __restrict__ x1,
    const float* __restrict__ x2, const float* __restrict__ x3,
    __nv_bfloat16* __restrict__ dst, size_t stride)
{
    const int z = blockIdx.y;
    const float* x = (z == 0) ? x0 : (z == 1) ? x1 : (z == 2) ? x2 : x3;
    const size_t i = ((size_t)blockIdx.x * 256 + threadIdx.x) * 4;
    float4 v = *(const float4*)(x + i);
    __nv_bfloat16 h[4];
    h[0] = __float2bfloat16(v.x);
    h[1] = __float2bfloat16(v.y);
    h[2] = __float2bfloat16(v.z);
    h[3] = __float2bfloat16(v.w);
    *(uint2*)(dst + (size_t)z * stride + i) = *(uint2*)h;
}

// ============================================================================
// Mask pack: int32 0/1 -> bit per key
// ============================================================================
__global__ __launch_bounds__(256) void mask_pack_kernel(const int* __restrict__ mask,
                                                        uint32_t* __restrict__ bits)
{
    const int warp = (blockIdx.x * blockDim.x + threadIdx.x) >> 5;
    const int lane = threadIdx.x & 31;
    const size_t base = (size_t)warp * 16 * 32;
    #pragma unroll
    for (int i = 0; i < 16; i++) {
        int v = mask[base + i * 32 + lane];
        unsigned bal = __ballot_sync(0xffffffffu, v != 0);
        if (lane == 0) bits[warp * 16 + i] = bal;
    }
}

// ============================================================================
// bf16 tensor-core GEMM, cp.async double-buffered, BK=32.
// MULTI: blockIdx.z selects A/W/bias/out slice (QKV merged).
// 128x128 tile, 8 warps (2m x 4n), warp tile 64x32.
// ============================================================================
#define AST 40    // A smem row stride (bf16): 80B -> ldsm conflict-free
#define BST 136   // B smem row stride (bf16): 272B -> ldsm.trans conflict-free
#define BK  32
#define NKT 24    // 768/32

template<bool MULTI, bool RESID, bool OUTBF16>
__global__ __launch_bounds__(256, 2) void gemm_tc_kernel(
    const __nv_bfloat16* __restrict__ Ag, const __nv_bfloat16* __restrict__ Wg,
    const float* __restrict__ b0, const float* __restrict__ b1,
    const float* __restrict__ b2,
    const float* __restrict__ resid, void* __restrict__ Cout)
{
    __shared__ __nv_bfloat16 As[2][128*AST];   // 20.5 KB
    __shared__ __nv_bfloat16 Bs[2][BK*BST];    // 17.4 KB

    const int z = MULTI ? blockIdx.z : 0;
    const float* bias = MULTI ? ((z == 0) ? b0 : (z == 1) ? b1 : b2) : b0;
    const size_t a_base = (size_t)z * M_TOT * DM;
    const size_t w_base = (size_t)z * DM * DM;

    const int tid  = threadIdx.x;
    const int wid  = tid >> 5;
    const int lane = tid & 31;
    const int m0   = blockIdx.y * 128;
    const int n0   = blockIdx.x * 128;
    const int warp_m = (wid & 1) * 64;
    const int warp_n = (wid >> 1) * 32;

    // staging: A 128x32 = 512 16B-chunks, 2/thread; B 32x128 same
    const int sar = tid >> 1;            // A row 0..127
    const int sac = (tid & 1) * 16;      // A col 0 or 16 (two chunks: +0,+8)
    const int sbr = tid >> 3;            // B k row 0..31
    const int sbc = (tid & 7) * 16;      // B n col (two chunks: +0,+8)

    const uint32_t as0 = smem_u32(As);
    const uint32_t bs0 = smem_u32(Bs);
    const uint32_t a_off = (uint32_t)(sar * AST + sac) * 2;
    const uint32_t b_off = (uint32_t)(sbr * BST + sbc) * 2;

    const __nv_bfloat16* a_src = Ag + a_base + (size_t)(m0 + sar) * DM + sac;
    const __nv_bfloat16* b_src = Wg + w_base + (size_t)sbr * DM + n0 + sbc;

    // ldmatrix lane addressing
    const int lrow = lane & 7;
    const int lsel = lane >> 3;
    const int arow_f = lrow + ((lsel & 1) ? 8 : 0);
    const int akb    = (lsel & 2) ? 16 : 0;            // byte offset (k half)
    const int bkr    = lrow + ((lsel & 1) ? 8 : 0);
    const int bn_sub = (lsel & 2) ? 8 : 0;

    float acc[4][4][4] = {};

    // prefetch stage 0
    {
        cpasync16(as0 + a_off,      a_src);
        cpasync16(as0 + a_off + 16, a_src + 8);
        cpasync16(bs0 + b_off,      b_src);
        cpasync16(bs0 + b_off + 16, b_src + 8);
        cp_commit();
    }

    for (int kt = 0; kt < NKT; kt++) {
        if (kt + 1 < NKT) {
            const int s  = (kt + 1) & 1;
            const int k0 = (kt + 1) * BK;
            const uint32_t sa = as0 + (uint32_t)(s * 128 * AST * 2);
            const uint32_t sb = bs0 + (uint32_t)(s * BK * BST * 2);
            cpasync16(sa + a_off,      a_src + k0);
            cpasync16(sa + a_off + 16, a_src + k0 + 8);
            cpasync16(sb + b_off,      b_src + (size_t)k0 * DM);
            cpasync16(sb + b_off + 16, b_src + (size_t)k0 * DM + 8);
            cp_commit();
            cp_wait<1>();
        } else {
            cp_wait<0>();
        }
        __syncthreads();

        const int s = kt & 1;
        const uint32_t as_s = as0 + (uint32_t)(s * 128 * AST * 2);
        const uint32_t bs_s = bs0 + (uint32_t)(s * BK * BST * 2);

        #pragma unroll
        for (int kk = 0; kk < 2; kk++) {
            uint32_t af[4][4];
            #pragma unroll
            for (int t = 0; t < 4; t++)
                ldsm4(af[t][0], af[t][1], af[t][2], af[t][3],
                      as_s + (uint32_t)((warp_m + t*16 + arow_f) * AST * 2 + kk*32 + akb));
            #pragma unroll
            for (int u = 0; u < 2; u++) {
                uint32_t r0, r1, r2, r3;
                ldsm4t(r0, r1, r2, r3,
                       bs_s + (uint32_t)((kk*16 + bkr) * BST * 2 + (warp_n + u*16 + bn_sub) * 2));
                #pragma unroll
                for (int t = 0; t < 4; t++) {
                    mma_bf16(acc[t][2*u],   af[t][0], af[t][1], af[t][2], af[t][3], r0, r1);
                    mma_bf16(acc[t][2*u+1], af[t][0], af[t][1], af[t][2], af[t][3], r2, r3);
                }
            }
        }
        __syncthreads();
    }

    // epilogue
    const int g  = lane >> 2;
    const int t4 = lane & 3;
    #pragma unroll
    for (int t = 0; t < 4; t++) {
        #pragma unroll
        for (int n = 0; n < 4; n++) {
            int row0 = m0 + warp_m + t*16 + g;
            int row1 = row0 + 8;
            int col  = n0 + warp_n + n*8 + t4*2;
            float2 bi = *(const float2*)(bias + col);
            float2 o0, o1;
            o0.x = acc[t][n][0] + bi.x;  o0.y = acc[t][n][1] + bi.y;
            o1.x = acc[t][n][2] + bi.x;  o1.y = acc[t][n][3] + bi.y;
            if (RESID) {
                float2 r0 = *(const float2*)(resid + (size_t)row0 * DM + col);
                float2 r1 = *(const float2*)(resid + (size_t)row1 * DM + col);
                o0.x += r0.x; o0.y += r0.y;
                o1.x += r1.x; o1.y += r1.y;
            }
            if (OUTBF16) {
                __nv_bfloat16* C = (__nv_bfloat16*)Cout + (size_t)z * M_TOT * DM;
                *(uint32_t*)(C + (size_t)row0 * DM + col) = pack_bf16(o0.x, o0.y);
                *(uint32_t*)(C + (size_t)row1 * DM + col) = pack_bf16(o1.x, o1.y);
            } else {
                float* C = (float*)Cout;
                *(float2*)(C + (size_t)row0 * DM + col) = o0;
                *(float2*)(C + (size_t)row1 * DM + col) = o1;
            }
        }
    }
}

// ============================================================================
// Tensor-core flash attention, cp.async double-buffered K/V.
// CTA: 128 q rows x one (b,h). 8 warps x 16 q rows. 64-key tiles.
// ============================================================================
#define KST 72
#define KV_STAGE_ELEMS (2 * 64 * KST)

__global__ __launch_bounds__(256, 2) void attn_tc_kernel(const uint32_t* __restrict__ mbits)
{
    __shared__ __nv_bfloat16 s_buf[2 * KV_STAGE_ELEMS];   // 36.9 KB

    const int tid  = threadIdx.x;
    const int wid  = tid >> 5;
    const int lane = tid & 31;
    const int b    = blockIdx.z;
    const int h    = blockIdx.y;
    const int q0   = blockIdx.x * 128;
    const int g    = lane >> 2;
    const int t4   = lane & 3;

    const __nv_bfloat16* qg = g_qkvb + 0 * (size_t)M_TOT * DM;
    const __nv_bfloat16* kg = g_qkvb + 1 * (size_t)M_TOT * DM + (size_t)(b * SS) * DM + h * DKH;
    const __nv_bfloat16* vg = g_qkvb + 2 * (size_t)M_TOT * DM + (size_t)(b * SS) * DM + h * DKH;

    // ---- stage Q tile [128 x 64] into s_buf (aliases stage 0) ----
    {
        const int r  = tid >> 1;
        const int hh = (tid & 1) * 32;
        const uint4* src = (const uint4*)(qg + (size_t)(b * SS + q0 + r) * DM + h * DKH + hh);
        uint4* dst = (uint4*)(s_buf + r * KST + hh);
        dst[0] = src[0]; dst[1] = src[1]; dst[2] = src[2]; dst[3] = src[3];
    }
    __syncthreads();

    // ---- Q fragments ----
    uint32_t qa[4][4];
    {
        const uint32_t base = smem_u32(s_buf);
        const int row  = wid * 16 + (lane & 15);
        const int colh = (lane >> 4) * 8;
        #pragma unroll
        for (int j = 0; j < 4; j++)
            ldsm4(qa[j][0], qa[j][1], qa[j][2], qa[j][3],
                  base + (uint32_t)((row * KST + j * 16 + colh) * 2));
    }
    __syncthreads();

    float o[8][4] = {};
    float ls0 = 0.f, ls1 = 0.f;

    const uint32_t* mrow0 = mbits + ((size_t)(b * SS + q0 + wid * 16 + g)) * (SS/32);
    const uint32_t* mrow1 = mrow0 + 8 * (SS/32);

    const uint32_t sb = smem_u32(s_buf);

    const int krow = (lane & 7) + ((lane >> 4) ? 8 : 0);
    const int kcol = ((lane >> 3) & 1) * 8;
    const int vrow = (lane & 7) + (((lane >> 3) & 1) ? 8 : 0);
    const int vcol = (lane >> 4) * 8;
    const uint32_t k_lane_off = (uint32_t)((krow * KST + kcol) * 2);
    const uint32_t v_lane_off = (uint32_t)((vrow * KST + vcol) * 2);

    const int c0   = tid * 2;
    const int srow = c0 >> 3;
    const int scol = (c0 & 7) * 8;
    const uint32_t st_off = (uint32_t)((srow * KST + scol) * 2);

    {
        const __nv_bfloat16* kp = kg + (size_t)srow * DM + scol;
        const __nv_bfloat16* vp = vg + (size_t)srow * DM + scol;
        cpasync16(sb + st_off, kp);
        cpasync16(sb + st_off + 16, kp + 8);
        cpasync16(sb + (uint32_t)(64*KST*2) + st_off, vp);
        cpasync16(sb + (uint32_t)(64*KST*2) + st_off + 16, vp + 8);
        cp_commit();
    }

    for (int kt = 0; kt < SS/64; kt++) {
        if (kt + 1 < SS/64) {
            const uint32_t s_off = (uint32_t)(((kt + 1) & 1) * KV_STAGE_ELEMS * 2);
            const __nv_bfloat16* kp = kg + (size_t)((kt+1)*64 + srow) * DM + scol;
            const __nv_bfloat16* vp = vg + (size_t)((kt+1)*64 + srow) * DM + scol;
            cpasync16(sb + s_off + st_off, kp);
            cpasync16(sb + s_off + st_off + 16, kp + 8);
            cpasync16(sb + s_off + (uint32_t)(64*KST*2) + st_off, vp);
            cpasync16(sb + s_off + (uint32_t)(64*KST*2) + st_off + 16, vp + 8);
            cp_commit();
            cp_wait<1>();
        } else {
            cp_wait<0>();
        }
        __syncthreads();

        const uint32_t stage = (uint32_t)((kt & 1) * KV_STAGE_ELEMS * 2);
        const uint32_t kaddr0 = sb + stage + k_lane_off;
        const uint32_t vaddr0 = sb + stage + (uint32_t)(64*KST*2) + v_lane_off;

        // ---- S = Q K^T ----
        float c[8][4] = {};
        #pragma unroll
        for (int np = 0; np < 4; np++) {
            #pragma unroll
            for (int j = 0; j < 4; j++) {
                uint32_t r0, r1, r2, r3;
                ldsm4(r0, r1, r2, r3, kaddr0 + (uint32_t)((np*16*KST + j*16) * 2));
                mma_bf16(c[2*np],   qa[j][0], qa[j][1], qa[j][2], qa[j][3], r0, r1);
                mma_bf16(c[2*np+1], qa[j][0], qa[j][1], qa[j][2], qa[j][3], r2, r3);
            }
        }

        // ---- mask + exp + row-sum ----
        const int k0 = kt * 64;
        const int kw = k0 >> 5;
        const uint32_t m0a = mrow0[kw], m0b = mrow0[kw+1];
        const uint32_t m1a = mrow1[kw], m1b = mrow1[kw+1];
        const float SC = 0.125f * 1.44269504088896340736f;
        #pragma unroll
        for (int nt = 0; nt < 8; nt++) {
            const int colb = nt * 8 + 2 * t4;
            const uint32_t w0 = (colb & 32) ? m0b : m0a;
            const uint32_t w1 = (colb & 32) ? m1b : m1a;
            const int bit = colb & 31;
            float p0 = ((w0 >> bit)     & 1u) ? 0.f : exp2f(c[nt][0] * SC);
            float p1 = ((w0 >> (bit+1)) & 1u) ? 0.f : exp2f(c[nt][1] * SC);
            float p2 = ((w1 >> bit)     & 1u) ? 0.f : exp2f(c[nt][2] * SC);
            float p3 = ((w1 >> (bit+1)) & 1u) ? 0.f : exp2f(c[nt][3] * SC);
            ls0 += p0 + p1;
            ls1 += p2 + p3;
            c[nt][0] = p0; c[nt][1] = p1; c[nt][2] = p2; c[nt][3] = p3;
        }

        // ---- repack P ----
        uint32_t pa[4][4];
        #pragma unroll
        for (int j = 0; j < 4; j++) {
            pa[j][0] = pack_bf16(c[2*j][0],   c[2*j][1]);
            pa[j][1] = pack_bf16(c[2*j][2],   c[2*j][3]);
            pa[j][2] = pack_bf16(c[2*j+1][0], c[2*j+1][1]);
            pa[j][3] = pack_bf16(c[2*j+1][2], c[2*j+1][3]);
        }

        // ---- O += P V ----
        #pragma unroll
        for (int np = 0; np < 4; np++) {
            #pragma unroll
            for (int j = 0; j < 4; j++) {
                uint32_t r0, r1, r2, r3;
                ldsm4t(r0, r1, r2, r3, vaddr0 + (uint32_t)((j*16*KST + np*16) * 2));
                mma_bf16(o[2*np],   pa[j][0], pa[j][1], pa[j][2], pa[j][3], r0, r1);
                mma_bf16(o[2*np+1], pa[j][0], pa[j][1], pa[j][2], pa[j][3], r2, r3);
            }
        }
        __syncthreads();
    }

    // ---- reduce, normalize, write ctx (bf16) ----
    ls0 += __shfl_xor_sync(0xffffffffu, ls0, 1);
    ls0 += __shfl_xor_sync(0xffffffffu, ls0, 2);
    ls1 += __shfl_xor_sync(0xffffffffu, ls1, 1);
    ls1 += __shfl_xor_sync(0xffffffffu, ls1, 2);
    const float inv0 = 1.f / ls0;
    const float inv1 = 1.f / ls1;

    const size_t r0off = (size_t)(b * SS + q0 + wid * 16 + g) * DM + h * DKH;
    const size_t r1off = r0off + 8 * DM;
    #pragma unroll
    for (int nt = 0; nt < 8; nt++) {
        const int col = nt * 8 + 2 * t4;
        *(uint32_t*)(g_ab + r0off + col) = pack_bf16(o[nt][0] * inv0, o[nt][1] * inv0);
        *(uint32_t*)(g_ab + r1off + col) = pack_bf16(o[nt][2] * inv1, o[nt][3] * inv1);
    }
}

// ============================================================================
// LayerNorm: 1 block per row, 256 threads, 3 elements each
// ============================================================================
__global__ __launch_bounds__(256) void ln_kernel(
    const float* __restrict__ x,
    const float* __restrict__ gamma, const float* __restrict__ beta,
    float* __restrict__ out)
{
    const int row = blockIdx.x;
    const int tid = threadIdx.x;
    const float* xr = x + (size_t)row * DM;

    float v0 = xr[tid];
    float v1 = xr[tid + 256];
    float v2 = xr[tid + 512];
    float s  = v0 + v1 + v2;
    float sq = v0 * v0 + v1 * v1 + v2 * v2;

    #pragma unroll
    for (int o = 16; o > 0; o >>= 1) {
        s  += __shfl_xor_sync(0xffffffffu, s,  o);
        sq += __shfl_xor_sync(0xffffffffu, sq, o);
    }
    __shared__ float reds[8], redq[8];
    const int wid = tid >> 5, lid = tid & 31;
    if (lid == 0) { reds[wid] = s; redq[wid] = sq; }
    __syncthreads();
    float ts = 0.f, tq = 0.f;
    #pragma unroll
    for (int i = 0; i < 8; i++) { ts += reds[i]; tq += redq[i]; }

    const float mu  = ts * (1.f / DM);
    const float var = tq * (1.f / DM) - mu * mu;
    const float rs  = rsqrtf(var + 1e-5f);

    float* orow = out + (size_t)row * DM;
    orow[tid]       = (v0 - mu) * rs * gamma[tid]       + beta[tid];
    orow[tid + 256] = (v1 - mu) * rs * gamma[tid + 256] + beta[tid + 256];
    orow[tid + 512] = (v2 - mu) * rs * gamma[tid + 512] + beta[tid + 512];
}

// ============================================================================
// Launch
// ============================================================================
extern "C" void kernel_launch(void* const* d_in, const int* in_sizes, int n_in,
                              void* d_out, int out_size)
{
    const float* Qin  = (const float*)d_in[0];
    const float* Kin  = (const float*)d_in[1];
    const float* Vin  = (const float*)d_in[2];
    const int*   mask = (const int*)d_in[3];
    const float* Wq = (const float*)d_in[4];
    const float* bq = (const float*)d_in[5];
    const float* Wk = (const float*)d_in[6];
    const float* bk = (const float*)d_in[7];
    const float* Wv = (const float*)d_in[8];
    const float* bv = (const float*)d_in[9];
    const float* Wo = (const float*)d_in[10];
    const float* bo = (const float*)d_in[11];
    const float* gamma = (const float*)d_in[12];
    const float* beta  = (const float*)d_in[13];
    float* out = (float*)d_out;

    __nv_bfloat16 *gqkv, *gab, *gwb;
    float* gtmp;
    uint32_t* gmb;
    cudaGetSymbolAddress((void**)&gqkv, g_qkvb);
    cudaGetSymbolAddress((void**)&gab,  g_ab);
    cudaGetSymbolAddress((void**)&gwb,  g_wb);
    cudaGetSymbolAddress((void**)&gtmp, g_tmp);
    cudaGetSymbolAddress((void**)&gmb,  g_mbits);

    mask_pack_kernel<<<4096, 256>>>(mask, gmb);

    // weight casts: 4 weights, 768*768/(256*4) = 576 blocks each
    cast4_kernel<<<dim3(576, 4), 256>>>(Wq, Wk, Wv, Wo, gwb, (size_t)DM * DM);

    // input casts: Q,K,V
    cast4_kernel<<<dim3(6144, 3), 256>>>(Qin, Kin, Vin, Qin, gab, (size_t)M_TOT * DM);

    // merged Q/K/V projection GEMM (1152 CTAs)
    gemm_tc_kernel<true, false, true><<<dim3(DM/128, M_TOT/128, 3), 256>>>(
        gab, gwb, bq, bk, bv, nullptr, gqkv);

    // attention (writes ctx bf16 into g_ab slice 0)
    attn_tc_kernel<<<dim3(SS / 128, NH, BB), 256>>>(gmb);

    // output projection + residual
    gemm_tc_kernel<false, true, false><<<dim3(DM/128, M_TOT/128), 256>>>(
        gab, gwb + 3*(size_t)DM*DM, bo, nullptr, nullptr, Qin, gtmp);

    ln_kernel<<<M_TOT, 256>>>(gtmp, gamma, beta, out);
}

// round 11
// speedup vs baseline: 16.5956x; 1.0669x over previous
#include <cuda_runtime.h>
#include <cuda_bf16.h>
#include <math.h>
#include <stdint.h>

#define BB     4
#define SS     2048
#define DM     768
#define NH     12
#define DKH    64
#define M_TOT  (BB*SS)   // 8192

// -------- scratch (static device arrays; no runtime allocation) --------
__device__ __nv_bfloat16 g_qkvb[3*M_TOT*DM];   // Q,K,V projections (bf16)
__device__ __nv_bfloat16 g_ab[3*M_TOT*DM];     // cast inputs / ctx (slice 0)
__device__ __nv_bfloat16 g_wb[4*DM*DM];        // cast weights x4
__device__ float    g_tmp[M_TOT*DM];
__device__ uint32_t g_mbits[BB*SS*(SS/32)];    // packed mask bits

// ============================================================================
// helpers
// ============================================================================
__device__ __forceinline__ uint32_t smem_u32(const void* p) {
    return (uint32_t)__cvta_generic_to_shared(p);
}
__device__ __forceinline__ void ldsm4(uint32_t& r0, uint32_t& r1, uint32_t& r2, uint32_t& r3, uint32_t addr) {
    asm volatile("ldmatrix.sync.aligned.m8n8.x4.shared.b16 {%0,%1,%2,%3}, [%4];"
                 : "=r"(r0), "=r"(r1), "=r"(r2), "=r"(r3) : "r"(addr));
}
__device__ __forceinline__ void ldsm4t(uint32_t& r0, uint32_t& r1, uint32_t& r2, uint32_t& r3, uint32_t addr) {
    asm volatile("ldmatrix.sync.aligned.m8n8.x4.trans.shared.b16 {%0,%1,%2,%3}, [%4];"
                 : "=r"(r0), "=r"(r1), "=r"(r2), "=r"(r3) : "r"(addr));
}
__device__ __forceinline__ void mma_bf16(float* c, uint32_t a0, uint32_t a1, uint32_t a2, uint32_t a3,
                                         uint32_t b0, uint32_t b1) {
    asm volatile("mma.sync.aligned.m16n8k16.row.col.f32.bf16.bf16.f32 "
                 "{%0,%1,%2,%3},{%4,%5,%6,%7},{%8,%9},{%0,%1,%2,%3};"
                 : "+f"(c[0]), "+f"(c[1]), "+f"(c[2]), "+f"(c[3])
                 : "r"(a0), "r"(a1), "r"(a2), "r"(a3), "r"(b0), "r"(b1));
}
__device__ __forceinline__ uint32_t pack_bf16(float x, float y) {
    __nv_bfloat162 p;
    p.x = __float2bfloat16(x);
    p.y = __float2bfloat16(y);
    return *(uint32_t*)&p;
}
__device__ __forceinline__ void cpasync16(uint32_t dst, const void* src) {
    asm volatile("cp.async.cg.shared.global [%0], [%1], 16;" :: "r"(dst), "l"(src));
}
__device__ __forceinline__ void cp_commit() { asm volatile("cp.async.commit_group;"); }
template<int N> __device__ __forceinline__ void cp_wait() {
    asm volatile("cp.async.wait_group %0;" :: "n"(N));
}

// ============================================================================
// fp32 -> bf16 cast; batched over blockIdx.y (up to 4 sources)
// ============================================================================
__global__ __launch_bounds__(256) void cast4_kernel(
    const float* __restrict__ x0, const float* __restrict__ x1,
    const float* __restrict__ x2, const float* __restrict__ x3,
    __nv_bfloat16* __restrict__ dst, size_t stride)
{
    const int z = blockIdx.y;
    const float* x = (z == 0) ? x0 : (z == 1) ? x1 : (z == 2) ? x2 : x3;
    const size_t i = ((size_t)blockIdx.x * 256 + threadIdx.x) * 4;
    float4 v = *(const float4*)(x + i);
    __nv_bfloat16 h[4];
    h[0] = __float2bfloat16(v.x);
    h[1] = __float2bfloat16(v.y);
    h[2] = __float2bfloat16(v.z);
    h[3] = __float2bfloat16(v.w);
    *(uint2*)(dst + (size_t)z * stride + i) = *(uint2*)h;
}

// ============================================================================
// Mask pack: int32 0/1 -> bit per key
// ============================================================================
__global__ __launch_bounds__(256) void mask_pack_kernel(const int* __restrict__ mask,
                                                        uint32_t* __restrict__ bits)
{
    const int warp = (blockIdx.x * blockDim.x + threadIdx.x) >> 5;
    const int lane = threadIdx.x & 31;
    const size_t base = (size_t)warp * 16 * 32;
    #pragma unroll
    for (int i = 0; i < 16; i++) {
        int v = mask[base + i * 32 + lane];
        unsigned bal = __ballot_sync(0xffffffffu, v != 0);
        if (lane == 0) bits[warp * 16 + i] = bal;
    }
}

// ============================================================================
// bf16 tensor-core GEMM, 3-stage cp.async ring, ONE barrier per k-step.
// MULTI: blockIdx.z selects A/W/bias/out slice (QKV merged).
// 128x128 tile, BK=32, 8 warps (2m x 4n), warp tile 64x32.
// ============================================================================
#define AST 40    // A smem row stride (bf16): 80B -> ldsm conflict-free
#define BST 136   // B smem row stride (bf16): 272B -> ldsm.trans conflict-free
#define BK  32
#define NKT 24    // 768/32
#define GSTAGES 3
#define A_STAGE_BYTES (128*AST*2)   // 10240
#define B_STAGE_BYTES (BK*BST*2)    // 8704
#define GEMM_SMEM (GSTAGES*(A_STAGE_BYTES+B_STAGE_BYTES))   // 56832

template<bool MULTI, bool RESID, bool OUTBF16>
__global__ __launch_bounds__(256, 2) void gemm_tc_kernel(
    const __nv_bfloat16* __restrict__ Ag, const __nv_bfloat16* __restrict__ Wg,
    const float* __restrict__ b0, const float* __restrict__ b1,
    const float* __restrict__ b2,
    const float* __restrict__ resid, void* __restrict__ Cout)
{
    extern __shared__ __nv_bfloat16 smg[];
    const uint32_t as0 = smem_u32(smg);
    const uint32_t bs0 = as0 + GSTAGES * A_STAGE_BYTES;

    const int z = MULTI ? blockIdx.z : 0;
    const float* bias = MULTI ? ((z == 0) ? b0 : (z == 1) ? b1 : b2) : b0;
    const size_t a_base = (size_t)z * M_TOT * DM;
    const size_t w_base = (size_t)z * DM * DM;

    const int tid  = threadIdx.x;
    const int wid  = tid >> 5;
    const int lane = tid & 31;
    const int m0   = blockIdx.y * 128;
    const int n0   = blockIdx.x * 128;
    const int warp_m = (wid & 1) * 64;
    const int warp_n = (wid >> 1) * 32;

    // staging: A 128x32 = 512 16B-chunks, 2/thread; B 32x128 same
    const int sar = tid >> 1;            // A row 0..127
    const int sac = (tid & 1) * 16;      // A col 0 or 16
    const int sbr = tid >> 3;            // B k row 0..31
    const int sbc = (tid & 7) * 16;      // B n col

    const uint32_t a_off = (uint32_t)(sar * AST + sac) * 2;
    const uint32_t b_off = (uint32_t)(sbr * BST + sbc) * 2;

    const __nv_bfloat16* a_src = Ag + a_base + (size_t)(m0 + sar) * DM + sac;
    const __nv_bfloat16* b_src = Wg + w_base + (size_t)sbr * DM + n0 + sbc;

    // ldmatrix lane addressing
    const int lrow = lane & 7;
    const int lsel = lane >> 3;
    const int arow_f = lrow + ((lsel & 1) ? 8 : 0);
    const int akb    = (lsel & 2) ? 16 : 0;
    const int bkr    = lrow + ((lsel & 1) ? 8 : 0);
    const int bn_sub = (lsel & 2) ? 8 : 0;

    float acc[4][4][4] = {};

    auto fill = [&](int kt) {
        const int s = kt % GSTAGES;
        const uint32_t sa = as0 + (uint32_t)(s * A_STAGE_BYTES);
        const uint32_t sb = bs0 + (uint32_t)(s * B_STAGE_BYTES);
        const int k0 = kt * BK;
        cpasync16(sa + a_off,      a_src + k0);
        cpasync16(sa + a_off + 16, a_src + k0 + 8);
        cpasync16(sb + b_off,      b_src + (size_t)k0 * DM);
        cpasync16(sb + b_off + 16, b_src + (size_t)k0 * DM + 8);
        cp_commit();
    };

    fill(0);
    fill(1);

    for (int kt = 0; kt < NKT; kt++) {
        if (kt == NKT - 1) cp_wait<0>(); else cp_wait<GSTAGES - 2>();
        __syncthreads();
        if (kt + GSTAGES - 1 < NKT) fill(kt + GSTAGES - 1);

        const int s = kt % GSTAGES;
        const uint32_t as_s = as0 + (uint32_t)(s * A_STAGE_BYTES);
        const uint32_t bs_s = bs0 + (uint32_t)(s * B_STAGE_BYTES);

        #pragma unroll
        for (int kk = 0; kk < 2; kk++) {
            uint32_t af[4][4];
            #pragma unroll
            for (int t = 0; t < 4; t++)
                ldsm4(af[t][0], af[t][1], af[t][2], af[t][3],
                      as_s + (uint32_t)((warp_m + t*16 + arow_f) * AST * 2 + kk*32 + akb));
            #pragma unroll
            for (int u = 0; u < 2; u++) {
                uint32_t r0, r1, r2, r3;
                ldsm4t(r0, r1, r2, r3,
                       bs_s + (uint32_t)((kk*16 + bkr) * BST * 2 + (warp_n + u*16 + bn_sub) * 2));
                #pragma unroll
                for (int t = 0; t < 4; t++) {
                    mma_bf16(acc[t][2*u],   af[t][0], af[t][1], af[t][2], af[t][3], r0, r1);
                    mma_bf16(acc[t][2*u+1], af[t][0], af[t][1], af[t][2], af[t][3], r2, r3);
                }
            }
        }
    }

    // epilogue
    const int g  = lane >> 2;
    const int t4 = lane & 3;
    #pragma unroll
    for (int t = 0; t < 4; t++) {
        #pragma unroll
        for (int n = 0; n < 4; n++) {
            int row0 = m0 + warp_m + t*16 + g;
            int row1 = row0 + 8;
            int col  = n0 + warp_n + n*8 + t4*2;
            float2 bi = *(const float2*)(bias + col);
            float2 o0, o1;
            o0.x = acc[t][n][0] + bi.x;  o0.y = acc[t][n][1] + bi.y;
            o1.x = acc[t][n][2] + bi.x;  o1.y = acc[t][n][3] + bi.y;
            if (RESID) {
                float2 r0 = *(const float2*)(resid + (size_t)row0 * DM + col);
                float2 r1 = *(const float2*)(resid + (size_t)row1 * DM + col);
                o0.x += r0.x; o0.y += r0.y;
                o1.x += r1.x; o1.y += r1.y;
            }
            if (OUTBF16) {
                __nv_bfloat16* C = (__nv_bfloat16*)Cout + (size_t)z * M_TOT * DM;
                *(uint32_t*)(C + (size_t)row0 * DM + col) = pack_bf16(o0.x, o0.y);
                *(uint32_t*)(C + (size_t)row1 * DM + col) = pack_bf16(o1.x, o1.y);
            } else {
                float* C = (float*)Cout;
                *(float2*)(C + (size_t)row0 * DM + col) = o0;
                *(float2*)(C + (size_t)row1 * DM + col) = o1;
            }
        }
    }
}

// ============================================================================
// Tensor-core flash attention, 3-stage cp.async ring, ONE barrier per tile.
// CTA: 128 q rows x one (b,h). 8 warps x 16 q rows. 64-key tiles.
// ============================================================================
#define KST 72
#define ATT_STAGE_BYTES (2 * 64 * KST * 2)   // K + V per stage = 18432
#define ASTAGES 3
#define ATT_SMEM (ASTAGES * ATT_STAGE_BYTES) // 55296
#define NTILES (SS/64)

__global__ __launch_bounds__(256, 2) void attn_tc_kernel(const uint32_t* __restrict__ mbits)
{
    extern __shared__ __nv_bfloat16 sma[];

    const int tid  = threadIdx.x;
    const int wid  = tid >> 5;
    const int lane = tid & 31;
    const int b    = blockIdx.z;
    const int h    = blockIdx.y;
    const int q0   = blockIdx.x * 128;
    const int g    = lane >> 2;
    const int t4   = lane & 3;

    const __nv_bfloat16* qg = g_qkvb + 0 * (size_t)M_TOT * DM;
    const __nv_bfloat16* kg = g_qkvb + 1 * (size_t)M_TOT * DM + (size_t)(b * SS) * DM + h * DKH;
    const __nv_bfloat16* vg = g_qkvb + 2 * (size_t)M_TOT * DM + (size_t)(b * SS) * DM + h * DKH;

    // ---- stage Q tile [128 x 64] into stage 0 area (exactly one stage) ----
    {
        const int r  = tid >> 1;
        const int hh = (tid & 1) * 32;
        const uint4* src = (const uint4*)(qg + (size_t)(b * SS + q0 + r) * DM + h * DKH + hh);
        uint4* dst = (uint4*)(sma + r * KST + hh);
        dst[0] = src[0]; dst[1] = src[1]; dst[2] = src[2]; dst[3] = src[3];
    }
    __syncthreads();

    // ---- Q fragments ----
    uint32_t qa[4][4];
    {
        const uint32_t base = smem_u32(sma);
        const int row  = wid * 16 + (lane & 15);
        const int colh = (lane >> 4) * 8;
        #pragma unroll
        for (int j = 0; j < 4; j++)
            ldsm4(qa[j][0], qa[j][1], qa[j][2], qa[j][3],
                  base + (uint32_t)((row * KST + j * 16 + colh) * 2));
    }
    __syncthreads();   // all warps done reading Q before stage-0 fill

    float o[8][4] = {};
    float ls0 = 0.f, ls1 = 0.f;

    const uint32_t* mrow0 = mbits + ((size_t)(b * SS + q0 + wid * 16 + g)) * (SS/32);
    const uint32_t* mrow1 = mrow0 + 8 * (SS/32);

    const uint32_t sb = smem_u32(sma);

    const int krow = (lane & 7) + ((lane >> 4) ? 8 : 0);
    const int kcol = ((lane >> 3) & 1) * 8;
    const int vrow = (lane & 7) + (((lane >> 3) & 1) ? 8 : 0);
    const int vcol = (lane >> 4) * 8;
    const uint32_t k_lane_off = (uint32_t)((krow * KST + kcol) * 2);
    const uint32_t v_lane_off = (uint32_t)((vrow * KST + vcol) * 2) + (uint32_t)(64*KST*2);

    const int c0   = tid * 2;
    const int srow = c0 >> 3;
    const int scol = (c0 & 7) * 8;
    const uint32_t st_off = (uint32_t)((srow * KST + scol) * 2);

    auto fill = [&](int kt) {
        const uint32_t base = sb + (uint32_t)((kt % ASTAGES) * ATT_STAGE_BYTES);
        const __nv_bfloat16* kp = kg + (size_t)(kt * 64 + srow) * DM + scol;
        const __nv_bfloat16* vp = vg + (size_t)(kt * 64 + srow) * DM + scol;
        cpasync16(base + st_off, kp);
        cpasync16(base + st_off + 16, kp + 8);
        cpasync16(base + (uint32_t)(64*KST*2) + st_off, vp);
        cpasync16(base + (uint32_t)(64*KST*2) + st_off + 16, vp + 8);
        cp_commit();
    };

    fill(0);
    fill(1);

    for (int kt = 0; kt < NTILES; kt++) {
        if (kt == NTILES - 1) cp_wait<0>(); else cp_wait<ASTAGES - 2>();
        __syncthreads();
        if (kt + ASTAGES - 1 < NTILES) fill(kt + ASTAGES - 1);

        const uint32_t stage = sb + (uint32_t)((kt % ASTAGES) * ATT_STAGE_BYTES);
        const uint32_t kaddr0 = stage + k_lane_off;
        const uint32_t vaddr0 = stage + v_lane_off;

        // ---- S = Q K^T ----
        float c[8][4] = {};
        #pragma unroll
        for (int np = 0; np < 4; np++) {
            #pragma unroll
            for (int j = 0; j < 4; j++) {
                uint32_t r0, r1, r2, r3;
                ldsm4(r0, r1, r2, r3, kaddr0 + (uint32_t)((np*16*KST + j*16) * 2));
                mma_bf16(c[2*np],   qa[j][0], qa[j][1], qa[j][2], qa[j][3], r0, r1);
                mma_bf16(c[2*np+1], qa[j][0], qa[j][1], qa[j][2], qa[j][3], r2, r3);
            }
        }

        // ---- mask + exp + row-sum ----
        const int k0 = kt * 64;
        const int kw = k0 >> 5;
        const uint32_t m0a = mrow0[kw], m0b = mrow0[kw+1];
        const uint32_t m1a = mrow1[kw], m1b = mrow1[kw+1];
        const float SC = 0.125f * 1.44269504088896340736f;
        #pragma unroll
        for (int nt = 0; nt < 8; nt++) {
            const int colb = nt * 8 + 2 * t4;
            const uint32_t w0 = (colb & 32) ? m0b : m0a;
            const uint32_t w1 = (colb & 32) ? m1b : m1a;
            const int bit = colb & 31;
            float p0 = ((w0 >> bit)     & 1u) ? 0.f : exp2f(c[nt][0] * SC);
            float p1 = ((w0 >> (bit+1)) & 1u) ? 0.f : exp2f(c[nt][1] * SC);
            float p2 = ((w1 >> bit)     & 1u) ? 0.f : exp2f(c[nt][2] * SC);
            float p3 = ((w1 >> (bit+1)) & 1u) ? 0.f : exp2f(c[nt][3] * SC);
            ls0 += p0 + p1;
            ls1 += p2 + p3;
            c[nt][0] = p0; c[nt][1] = p1; c[nt][2] = p2; c[nt][3] = p3;
        }

        // ---- repack P (C-frag -> A-frag) ----
        uint32_t pa[4][4];
        #pragma unroll
        for (int j = 0; j < 4; j++) {
            pa[j][0] = pack_bf16(c[2*j][0],   c[2*j][1]);
            pa[j][1] = pack_bf16(c[2*j][2],   c[2*j][3]);
            pa[j][2] = pack_bf16(c[2*j+1][0], c[2*j+1][1]);
            pa[j][3] = pack_bf16(c[2*j+1][2], c[2*j+1][3]);
        }

        // ---- O += P V ----
        #pragma unroll
        for (int np = 0; np < 4; np++) {
            #pragma unroll
            for (int j = 0; j < 4; j++) {
                uint32_t r0, r1, r2, r3;
                ldsm4t(r0, r1, r2, r3, vaddr0 + (uint32_t)((j*16*KST + np*16) * 2));
                mma_bf16(o[2*np],   pa[j][0], pa[j][1], pa[j][2], pa[j][3], r0, r1);
                mma_bf16(o[2*np+1], pa[j][0], pa[j][1], pa[j][2], pa[j][3], r2, r3);
            }
        }
    }

    // ---- reduce, normalize, write ctx (bf16) ----
    ls0 += __shfl_xor_sync(0xffffffffu, ls0, 1);
    ls0 += __shfl_xor_sync(0xffffffffu, ls0, 2);
    ls1 += __shfl_xor_sync(0xffffffffu, ls1, 1);
    ls1 += __shfl_xor_sync(0xffffffffu, ls1, 2);
    const float inv0 = 1.f / ls0;
    const float inv1 = 1.f / ls1;

    const size_t r0off = (size_t)(b * SS + q0 + wid * 16 + g) * DM + h * DKH;
    const size_t r1off = r0off + 8 * DM;
    #pragma unroll
    for (int nt = 0; nt < 8; nt++) {
        const int col = nt * 8 + 2 * t4;
        *(uint32_t*)(g_ab + r0off + col) = pack_bf16(o[nt][0] * inv0, o[nt][1] * inv0);
        *(uint32_t*)(g_ab + r1off + col) = pack_bf16(o[nt][2] * inv1, o[nt][3] * inv1);
    }
}

// ============================================================================
// LayerNorm: 1 block per row, 256 threads, 3 elements each
// ============================================================================
__global__ __launch_bounds__(256) void ln_kernel(
    const float* __restrict__ x,
    const float* __restrict__ gamma, const float* __restrict__ beta,
    float* __restrict__ out)
{
    const int row = blockIdx.x;
    const int tid = threadIdx.x;
    const float* xr = x + (size_t)row * DM;

    float v0 = xr[tid];
    float v1 = xr[tid + 256];
    float v2 = xr[tid + 512];
    float s  = v0 + v1 + v2;
    float sq = v0 * v0 + v1 * v1 + v2 * v2;

    #pragma unroll
    for (int o = 16; o > 0; o >>= 1) {
        s  += __shfl_xor_sync(0xffffffffu, s,  o);
        sq += __shfl_xor_sync(0xffffffffu, sq, o);
    }
    __shared__ float reds[8], redq[8];
    const int wid = tid >> 5, lid = tid & 31;
    if (lid == 0) { reds[wid] = s; redq[wid] = sq; }
    __syncthreads();
    float ts = 0.f, tq = 0.f;
    #pragma unroll
    for (int i = 0; i < 8; i++) { ts += reds[i]; tq += redq[i]; }

    const float mu  = ts * (1.f / DM);
    const float var = tq * (1.f / DM) - mu * mu;
    const float rs  = rsqrtf(var + 1e-5f);

    float* orow = out + (size_t)row * DM;
    orow[tid]       = (v0 - mu) * rs * gamma[tid]       + beta[tid];
    orow[tid + 256] = (v1 - mu) * rs * gamma[tid + 256] + beta[tid + 256];
    orow[tid + 512] = (v2 - mu) * rs * gamma[tid + 512] + beta[tid + 512];
}

// ============================================================================
// Launch
// ============================================================================
extern "C" void kernel_launch(void* const* d_in, const int* in_sizes, int n_in,
                              void* d_out, int out_size)
{
    const float* Qin  = (const float*)d_in[0];
    const float* Kin  = (const float*)d_in[1];
    const float* Vin  = (const float*)d_in[2];
    const int*   mask = (const int*)d_in[3];
    const float* Wq = (const float*)d_in[4];
    const float* bq = (const float*)d_in[5];
    const float* Wk = (const float*)d_in[6];
    const float* bk = (const float*)d_in[7];
    const float* Wv = (const float*)d_in[8];
    const float* bv = (const float*)d_in[9];
    const float* Wo = (const float*)d_in[10];
    const float* bo = (const float*)d_in[11];
    const float* gamma = (const float*)d_in[12];
    const float* beta  = (const float*)d_in[13];
    float* out = (float*)d_out;

    __nv_bfloat16 *gqkv, *gab, *gwb;
    float* gtmp;
    uint32_t* gmb;
    cudaGetSymbolAddress((void**)&gqkv, g_qkvb);
    cudaGetSymbolAddress((void**)&gab,  g_ab);
    cudaGetSymbolAddress((void**)&gwb,  g_wb);
    cudaGetSymbolAddress((void**)&gtmp, g_tmp);
    cudaGetSymbolAddress((void**)&gmb,  g_mbits);

    cudaFuncSetAttribute(gemm_tc_kernel<true, false, true>,
                         cudaFuncAttributeMaxDynamicSharedMemorySize, GEMM_SMEM);
    cudaFuncSetAttribute(gemm_tc_kernel<false, true, false>,
                         cudaFuncAttributeMaxDynamicSharedMemorySize, GEMM_SMEM);
    cudaFuncSetAttribute(attn_tc_kernel,
                         cudaFuncAttributeMaxDynamicSharedMemorySize, ATT_SMEM);

    mask_pack_kernel<<<4096, 256>>>(mask, gmb);

    // weight casts
    cast4_kernel<<<dim3(576, 4), 256>>>(Wq, Wk, Wv, Wo, gwb, (size_t)DM * DM);

    // input casts: Q,K,V
    cast4_kernel<<<dim3(6144, 3), 256>>>(Qin, Kin, Vin, Qin, gab, (size_t)M_TOT * DM);

    // merged Q/K/V projection GEMM (1152 CTAs)
    gemm_tc_kernel<true, false, true><<<dim3(DM/128, M_TOT/128, 3), 256, GEMM_SMEM>>>(
        gab, gwb, bq, bk, bv, nullptr, gqkv);

    // attention (writes ctx bf16 into g_ab slice 0)
    attn_tc_kernel<<<dim3(SS / 128, NH, BB), 256, ATT_SMEM>>>(gmb);

    // output projection + residual
    gemm_tc_kernel<false, true, false><<<dim3(DM/128, M_TOT/128), 256, GEMM_SMEM>>>(
        gab, gwb + 3*(size_t)DM*DM, bo, nullptr, nullptr, Qin, gtmp);

    ln_kernel<<<M_TOT, 256>>>(gtmp, gamma, beta, out);
}